// round 4
// baseline (speedup 1.0000x reference)
#include <cuda_runtime.h>
#include <cuda_fp16.h>
#include <cstdint>

// Problem constants
#define B_   4
#define T_   2048
#define D_   2048
#define H_   16
#define HD_  128
#define DFF_ 8192
#define R_   (B_*T_)      // 8192 rows

// ------------------------------------------------------------------
// Device scratch
// ------------------------------------------------------------------
__device__ __align__(256) __half g_h  [(size_t)R_*D_];
__device__ __align__(256) __half g_h2 [(size_t)R_*D_];
__device__ __align__(256) __half g_Wq [(size_t)H_*D_*HD_];
__device__ __align__(256) __half g_Wk [(size_t)H_*D_*HD_];
__device__ __align__(256) __half g_Wv [(size_t)H_*D_*HD_];
__device__ __align__(256) __half g_W1 [(size_t)D_*DFF_];
__device__ __align__(256) __half g_W2 [(size_t)DFF_*D_];
__device__ __align__(256) __half g_q  [(size_t)B_*H_*T_*HD_];
__device__ __align__(256) __half g_k  [(size_t)B_*H_*T_*HD_];
__device__ __align__(256) __half g_v  [(size_t)B_*H_*T_*HD_];
__device__ __align__(256) __half g_att[(size_t)R_*D_];
__device__ __align__(256) __half g_ff [(size_t)R_*DFF_];

// ------------------------------------------------------------------
// Helpers
// ------------------------------------------------------------------
__device__ __forceinline__ uint32_t smem_u32(const void* p) {
    return (uint32_t)__cvta_generic_to_shared(p);
}
__device__ __forceinline__ void cp16(uint32_t dst, const void* src) {
    asm volatile("cp.async.cg.shared.global [%0], [%1], 16;" :: "r"(dst), "l"(src));
}
#define CP_COMMIT() asm volatile("cp.async.commit_group;")
#define CP_WAIT0()  asm volatile("cp.async.wait_group 0;")
#define CP_WAIT1()  asm volatile("cp.async.wait_group 1;")

__device__ __forceinline__ void ldsm_x4(uint32_t& r0, uint32_t& r1, uint32_t& r2, uint32_t& r3, uint32_t a) {
    asm volatile("ldmatrix.sync.aligned.m8n8.x4.shared.b16 {%0,%1,%2,%3}, [%4];"
                 : "=r"(r0), "=r"(r1), "=r"(r2), "=r"(r3) : "r"(a));
}
__device__ __forceinline__ void ldsm_x4_t(uint32_t& r0, uint32_t& r1, uint32_t& r2, uint32_t& r3, uint32_t a) {
    asm volatile("ldmatrix.sync.aligned.m8n8.x4.trans.shared.b16 {%0,%1,%2,%3}, [%4];"
                 : "=r"(r0), "=r"(r1), "=r"(r2), "=r"(r3) : "r"(a));
}
__device__ __forceinline__ void mma_16816(float* c, const uint32_t* a, uint32_t b0, uint32_t b1v) {
    asm volatile(
        "mma.sync.aligned.m16n8k16.row.col.f32.f16.f16.f32 "
        "{%0,%1,%2,%3}, {%4,%5,%6,%7}, {%8,%9}, {%0,%1,%2,%3};\n"
        : "+f"(c[0]), "+f"(c[1]), "+f"(c[2]), "+f"(c[3])
        : "r"(a[0]), "r"(a[1]), "r"(a[2]), "r"(a[3]), "r"(b0), "r"(b1v));
}
__device__ __forceinline__ uint32_t packh2(float a, float b) {
    __half2 h = __floats2half2_rn(a, b);
    return *reinterpret_cast<uint32_t*>(&h);
}

// ------------------------------------------------------------------
// fp32 -> fp16 conversion, 8 elems/thread
// ------------------------------------------------------------------
__global__ void f2h_kernel(const float4* __restrict__ src, uint4* __restrict__ dst, int n8) {
    int i = blockIdx.x * blockDim.x + threadIdx.x;
    if (i >= n8) return;
    float4 a = src[2*i], b = src[2*i + 1];
    __half2 h0 = __floats2half2_rn(a.x, a.y);
    __half2 h1 = __floats2half2_rn(a.z, a.w);
    __half2 h2 = __floats2half2_rn(b.x, b.y);
    __half2 h3 = __floats2half2_rn(b.z, b.w);
    uint4 o;
    o.x = *(uint32_t*)&h0; o.y = *(uint32_t*)&h1;
    o.z = *(uint32_t*)&h2; o.w = *(uint32_t*)&h3;
    dst[i] = o;
}

// ------------------------------------------------------------------
// LayerNorm (block per row of D_=2048, 256 threads)
// ------------------------------------------------------------------
__global__ void __launch_bounds__(256) ln_kernel(
    const float* __restrict__ x, const float* __restrict__ g,
    const float* __restrict__ b, __half* __restrict__ out)
{
    int r = blockIdx.x;
    size_t off = (size_t)r * D_;
    float v[8], s = 0.f, s2 = 0.f;
#pragma unroll
    for (int j = 0; j < 8; j++) {
        float val = x[off + threadIdx.x + j*256];
        v[j] = val; s += val; s2 += val*val;
    }
    __shared__ float red[32];
#pragma unroll
    for (int o = 16; o; o >>= 1) { s += __shfl_xor_sync(~0u, s, o); s2 += __shfl_xor_sync(~0u, s2, o); }
    int wid = threadIdx.x >> 5;
    if ((threadIdx.x & 31) == 0) { red[wid] = s; red[8 + wid] = s2; }
    __syncthreads();
    if (threadIdx.x < 32) {
        float a  = (threadIdx.x < 8) ? red[threadIdx.x]   : 0.f;
        float c2 = (threadIdx.x < 8) ? red[8+threadIdx.x] : 0.f;
#pragma unroll
        for (int o = 4; o; o >>= 1) { a += __shfl_xor_sync(~0u, a, o); c2 += __shfl_xor_sync(~0u, c2, o); }
        if (threadIdx.x == 0) { red[16] = a; red[17] = c2; }
    }
    __syncthreads();
    float mu  = red[16] * (1.f / D_);
    float var = red[17] * (1.f / D_) - mu * mu;
    float rs  = rsqrtf(var + 1e-5f);
#pragma unroll
    for (int j = 0; j < 8; j++) {
        int c = threadIdx.x + j*256;
        out[off + c] = __float2half((v[j] - mu) * rs * g[c] + b[c]);
    }
}

// Fused: x1 = x + att ; write x1 to xout (fp32) ; h2 = LN(x1)
__global__ void __launch_bounds__(256) resid_ln_kernel(
    const float* __restrict__ x, const float* __restrict__ g,
    const float* __restrict__ b, float* __restrict__ xout,
    __half* __restrict__ h2)
{
    int r = blockIdx.x;
    size_t off = (size_t)r * D_;
    float v[8], s = 0.f, s2 = 0.f;
#pragma unroll
    for (int j = 0; j < 8; j++) {
        int c = threadIdx.x + j*256;
        float val = x[off + c] + __half2float(g_att[off + c]);
        xout[off + c] = val;
        v[j] = val; s += val; s2 += val*val;
    }
    __shared__ float red[32];
#pragma unroll
    for (int o = 16; o; o >>= 1) { s += __shfl_xor_sync(~0u, s, o); s2 += __shfl_xor_sync(~0u, s2, o); }
    int wid = threadIdx.x >> 5;
    if ((threadIdx.x & 31) == 0) { red[wid] = s; red[8 + wid] = s2; }
    __syncthreads();
    if (threadIdx.x < 32) {
        float a  = (threadIdx.x < 8) ? red[threadIdx.x]   : 0.f;
        float c2 = (threadIdx.x < 8) ? red[8+threadIdx.x] : 0.f;
#pragma unroll
        for (int o = 4; o; o >>= 1) { a += __shfl_xor_sync(~0u, a, o); c2 += __shfl_xor_sync(~0u, c2, o); }
        if (threadIdx.x == 0) { red[16] = a; red[17] = c2; }
    }
    __syncthreads();
    float mu  = red[16] * (1.f / D_);
    float var = red[17] * (1.f / D_) - mu * mu;
    float rs  = rsqrtf(var + 1e-5f);
#pragma unroll
    for (int j = 0; j < 8; j++) {
        int c = threadIdx.x + j*256;
        h2[off + c] = __float2half((v[j] - mu) * rs * g[c] + b[c]);
    }
}

// ------------------------------------------------------------------
// GEMM: C[M,N] = A[M,K]*B[K,N], 3-stage cp.async, ldmatrix, swizzled.
// BM=128, BN=256, BK=64; 256 threads (2x4 warps), warp tile 64x64.
//   mode 0: QKV   mode 1: FFN1 (relu)   mode 2: FFN2 (xout += C + b2)
// ------------------------------------------------------------------
#define BM 128
#define BN 256
#define BK 64
#define ASTG (BM*BK*2)            // 16384 B
#define BSTG (BK*BN*2)            // 32768 B
#define STG  (ASTG + BSTG)        // 49152 B
#define GSMEM (3*STG)             // 147456 B

__global__ void __launch_bounds__(256, 1) gemm_kernel(
    int mode,
    const float* __restrict__ bq, const float* __restrict__ bk, const float* __restrict__ bv,
    const float* __restrict__ b1, const float* __restrict__ b2,
    float* __restrict__ xout)
{
    const __half* A; int K;
    if (mode == 0)      { A = g_h;  K = D_;   }
    else if (mode == 1) { A = g_h2; K = D_;   }
    else                { A = g_ff; K = DFF_; }

    const int m0 = blockIdx.y * BM;
    const int n0 = blockIdx.x * BN;
    const int nkt = K / BK;

    extern __shared__ __half dsm[];
    const uint32_t sbase = smem_u32(dsm);

    const int tid  = threadIdx.x;
    const int wid  = tid >> 5;
    const int lane = tid & 31;
    const int wm   = wid & 1;               // 0..1 (M half)
    const int wn   = wid >> 1;              // 0..3 (N quarter)

    float acc[4][8][4];
#pragma unroll
    for (int i = 0; i < 4; i++)
#pragma unroll
        for (int j = 0; j < 8; j++)
#pragma unroll
            for (int q = 0; q < 4; q++) acc[i][j][q] = 0.f;

    // ---- stage loader ----
    auto loadStage = [&](int kt, int s) {
        uint32_t sA = sbase + s * STG;
        uint32_t sB = sA + ASTG;
        // A: 128x64, row = 8 chunks of 8 half
#pragma unroll
        for (int i = 0; i < 4; i++) {
            int idx = tid + i * 256;
            int r = idx >> 3, c = idx & 7;
            int sc = c ^ (r & 7);
            cp16(sA + r * 128 + sc * 16, A + (size_t)(m0 + r) * K + kt * BK + c * 8);
        }
        // B: 64x256, row = 32 chunks of 8 half
#pragma unroll
        for (int i = 0; i < 8; i++) {
            int idx = tid + i * 256;
            int r = idx >> 5, c = idx & 31;
            int sc = ((c & 7) ^ (r & 7)) | (c & 24);
            int n = n0 + c * 8;
            const __half* src;
            if (mode == 0) {
                int which = n >> 11, head = (n >> 7) & 15, e = n & 127;
                const __half* W = (which == 0) ? g_Wq : (which == 1) ? g_Wk : g_Wv;
                src = W + (size_t)head * (D_ * HD_) + (size_t)(kt * BK + r) * HD_ + e;
            } else if (mode == 1) {
                src = g_W1 + (size_t)(kt * BK + r) * DFF_ + n;
            } else {
                src = g_W2 + (size_t)(kt * BK + r) * D_ + n;
            }
            cp16(sB + r * 512 + sc * 16, src);
        }
    };

    loadStage(0, 0); CP_COMMIT();
    loadStage(1, 1); CP_COMMIT();

    for (int kt = 0; kt < nkt; kt++) {
        if (kt + 1 < nkt) { CP_WAIT1(); } else { CP_WAIT0(); }
        __syncthreads();
        if (kt + 2 < nkt) { loadStage(kt + 2, (kt + 2) % 3); CP_COMMIT(); }

        uint32_t sA = sbase + (kt % 3) * STG;
        uint32_t sB = sA + ASTG;

#pragma unroll
        for (int kk = 0; kk < 4; kk++) {
            uint32_t a[4][4];
#pragma unroll
            for (int mt = 0; mt < 4; mt++) {
                int row = wm * 64 + mt * 16 + (lane & 15);
                int ch  = 2 * kk + (lane >> 4);
                ldsm_x4(a[mt][0], a[mt][1], a[mt][2], a[mt][3],
                        sA + row * 128 + ((ch ^ (row & 7)) << 4));
            }
            uint32_t bf[8][2];
#pragma unroll
            for (int g = 0; g < 4; g++) {
                int row = kk * 16 + ((lane >> 3) & 1) * 8 + (lane & 7);
                int ch  = wn * 8 + g * 2 + (lane >> 4);
                int sc  = ((ch & 7) ^ (row & 7)) | (ch & 24);
                ldsm_x4_t(bf[2*g][0], bf[2*g][1], bf[2*g+1][0], bf[2*g+1][1],
                          sB + row * 512 + sc * 16);
            }
#pragma unroll
            for (int nt = 0; nt < 8; nt++)
#pragma unroll
                for (int mt = 0; mt < 4; mt++)
                    mma_16816(acc[mt][nt], a[mt], bf[nt][0], bf[nt][1]);
        }
    }

    // ---- Epilogue ----
    const int nw0 = n0 + wn * 64;               // warp's 64-col slab (within one head for mode 0)
    if (mode == 0) {
        int which = nw0 >> 11, head = (nw0 >> 7) & 15;
        const float* bias = ((which == 0) ? bq : (which == 1) ? bk : bv) + head * HD_;
        __half* qkv = (which == 0) ? g_q : (which == 1) ? g_k : g_v;
#pragma unroll
        for (int mt = 0; mt < 4; mt++) {
#pragma unroll
            for (int nt = 0; nt < 8; nt++) {
                float* cc = acc[mt][nt];
                int row0 = m0 + wm * 64 + mt * 16 + (lane >> 2);
                int e    = (nw0 & 127) + nt * 8 + ((lane & 3) << 1);
                float bb0 = bias[e], bb1 = bias[e + 1];
#pragma unroll
                for (int rr = 0; rr < 2; rr++) {
                    int row = row0 + rr * 8;
                    int bb = row >> 11, t = row & (T_ - 1);
                    __half* dst = qkv + (((size_t)(bb * H_ + head) * T_ + t) * HD_) + e;
                    *(__half2*)dst = __floats2half2_rn(cc[rr*2] + bb0, cc[rr*2+1] + bb1);
                }
            }
        }
    } else if (mode == 1) {
#pragma unroll
        for (int mt = 0; mt < 4; mt++) {
#pragma unroll
            for (int nt = 0; nt < 8; nt++) {
                float* cc = acc[mt][nt];
                int row0 = m0 + wm * 64 + mt * 16 + (lane >> 2);
                int col  = nw0 + nt * 8 + ((lane & 3) << 1);
                float bb0 = b1[col], bb1 = b1[col + 1];
#pragma unroll
                for (int rr = 0; rr < 2; rr++) {
                    int row = row0 + rr * 8;
                    float v0 = fmaxf(cc[rr*2]   + bb0, 0.f);
                    float v1 = fmaxf(cc[rr*2+1] + bb1, 0.f);
                    *(__half2*)(g_ff + (size_t)row * DFF_ + col) = __floats2half2_rn(v0, v1);
                }
            }
        }
    } else {
#pragma unroll
        for (int mt = 0; mt < 4; mt++) {
#pragma unroll
            for (int nt = 0; nt < 8; nt++) {
                float* cc = acc[mt][nt];
                int row0 = m0 + wm * 64 + mt * 16 + (lane >> 2);
                int col  = nw0 + nt * 8 + ((lane & 3) << 1);
                float bb0 = b2[col], bb1 = b2[col + 1];
#pragma unroll
                for (int rr = 0; rr < 2; rr++) {
                    int row = row0 + rr * 8;
                    float2* d = (float2*)(xout + (size_t)row * D_ + col);
                    float2 val = *d;
                    val.x += cc[rr*2]   + bb0;
                    val.y += cc[rr*2+1] + bb1;
                    *d = val;
                }
            }
        }
    }
}

// ------------------------------------------------------------------
// Flash attention: grid (T/128, B*H), 256 threads (8 warps x 16 q rows)
// Double-buffered cp.async K/V, ldmatrix fragments.
// ------------------------------------------------------------------
#define AQ 128
#define AK 64
#define AKVSTG (AK*HD_*2)          // 16384 B per tensor per stage
#define ASMEM  (4*AKVSTG)          // 65536 B (2 stages x K,V)

__global__ void __launch_bounds__(256, 1) attn_kernel() {
    const int bh = blockIdx.y;
    const int b  = bh >> 4, h = bh & 15;
    const int t0 = blockIdx.x * AQ;

    const __half* qbase = g_q + (size_t)bh * T_ * HD_;
    const __half* kbase = g_k + (size_t)bh * T_ * HD_;
    const __half* vbase = g_v + (size_t)bh * T_ * HD_;

    extern __shared__ __half kvsm[];
    const uint32_t kvbase = smem_u32(kvsm);

    const int tid  = threadIdx.x;
    const int wid  = tid >> 5;
    const int lane = tid & 31;
    const int qr   = wid * 16 + (lane >> 2);

    // Q fragments in registers
    uint32_t qa[8][4];
    {
        const __half* qp = qbase + (size_t)t0 * HD_;
#pragma unroll
        for (int kk = 0; kk < 8; kk++) {
            int c = ((lane & 3) << 1) + kk * 16;
            qa[kk][0] = *(const uint32_t*)(qp + (size_t)qr       * HD_ + c);
            qa[kk][1] = *(const uint32_t*)(qp + (size_t)(qr + 8) * HD_ + c);
            qa[kk][2] = *(const uint32_t*)(qp + (size_t)qr       * HD_ + c + 8);
            qa[kk][3] = *(const uint32_t*)(qp + (size_t)(qr + 8) * HD_ + c + 8);
        }
    }

    float m_run[2] = {-1e30f, -1e30f};
    float l_run[2] = {0.f, 0.f};
    float o[16][4];
#pragma unroll
    for (int i = 0; i < 16; i++)
#pragma unroll
        for (int q = 0; q < 4; q++) o[i][q] = 0.f;

    const float scale = 0.08838834764831845f;
    const int jmax = (t0 + AQ - 1) / AK;

    auto loadKV = [&](int j, int s) {
        uint32_t kb = kvbase + s * (2 * AKVSTG);
        uint32_t vb = kb + AKVSTG;
        const __half* ks = kbase + (size_t)(j * AK) * HD_;
        const __half* vs = vbase + (size_t)(j * AK) * HD_;
#pragma unroll
        for (int i = 0; i < 4; i++) {
            int idx = tid + i * 256;
            int row = idx >> 4, ch = idx & 15;
            int sc = ((ch & 7) ^ (row & 7)) | (ch & 8);
            cp16(kb + row * 256 + sc * 16, ks + (size_t)row * HD_ + ch * 8);
            cp16(vb + row * 256 + sc * 16, vs + (size_t)row * HD_ + ch * 8);
        }
    };

    loadKV(0, 0); CP_COMMIT();

    for (int j = 0; j <= jmax; j++) {
        const int s0 = j * AK;
        __syncthreads();      // prior compute done before overwriting buffer
        if (j + 1 <= jmax) { loadKV(j + 1, (j + 1) & 1); CP_COMMIT(); CP_WAIT1(); }
        else               { CP_WAIT0(); }
        __syncthreads();

        uint32_t Kb = kvbase + (j & 1) * (2 * AKVSTG);
        uint32_t Vb = Kb + AKVSTG;

        // S = Q K^T
        float sacc[8][4];
#pragma unroll
        for (int nt = 0; nt < 8; nt++)
#pragma unroll
            for (int q = 0; q < 4; q++) sacc[nt][q] = 0.f;

#pragma unroll
        for (int kk = 0; kk < 8; kk++) {
#pragma unroll
            for (int ntp = 0; ntp < 4; ntp++) {
                int row = ntp * 16 + ((lane >> 4) << 3) + (lane & 7);
                int ch  = 2 * kk + ((lane >> 3) & 1);
                int sc  = ((ch & 7) ^ (row & 7)) | (ch & 8);
                uint32_t r0, r1, r2, r3;
                ldsm_x4(r0, r1, r2, r3, Kb + row * 256 + sc * 16);
                mma_16816(sacc[2*ntp],   qa[kk], r0, r1);
                mma_16816(sacc[2*ntp+1], qa[kk], r2, r3);
            }
        }

        // scale + causal mask + tile max
        const int tg0 = t0 + wid * 16 + (lane >> 2);
        float mtile[2] = {-1e30f, -1e30f};
#pragma unroll
        for (int nt = 0; nt < 8; nt++) {
            int sg = s0 + nt * 8 + ((lane & 3) << 1);
#pragma unroll
            for (int q = 0; q < 4; q++) {
                int rsel = q >> 1;
                int scol = sg + (q & 1);
                int tg   = tg0 + (rsel ? 8 : 0);
                float vv = sacc[nt][q] * scale;
                if (scol > tg) vv = -1e30f;
                sacc[nt][q] = vv;
                mtile[rsel] = fmaxf(mtile[rsel], vv);
            }
        }
#pragma unroll
        for (int o2 = 1; o2 < 4; o2 <<= 1) {
            mtile[0] = fmaxf(mtile[0], __shfl_xor_sync(~0u, mtile[0], o2));
            mtile[1] = fmaxf(mtile[1], __shfl_xor_sync(~0u, mtile[1], o2));
        }
        float mnew[2] = {fmaxf(m_run[0], mtile[0]), fmaxf(m_run[1], mtile[1])};
        float corr[2] = {__expf(m_run[0] - mnew[0]), __expf(m_run[1] - mnew[1])};

        // P = exp(S - m)
        float pl[2] = {0.f, 0.f};
        uint32_t pa[4][4];
#pragma unroll
        for (int nt = 0; nt < 8; nt++) {
            float p0 = __expf(sacc[nt][0] - mnew[0]);
            float p1 = __expf(sacc[nt][1] - mnew[0]);
            float p2 = __expf(sacc[nt][2] - mnew[1]);
            float p3 = __expf(sacc[nt][3] - mnew[1]);
            pl[0] += p0 + p1; pl[1] += p2 + p3;
            int kk2 = nt >> 1, hi = nt & 1;
            pa[kk2][2*hi]     = packh2(p0, p1);
            pa[kk2][2*hi + 1] = packh2(p2, p3);
        }
#pragma unroll
        for (int o2 = 1; o2 < 4; o2 <<= 1) {
            pl[0] += __shfl_xor_sync(~0u, pl[0], o2);
            pl[1] += __shfl_xor_sync(~0u, pl[1], o2);
        }
        l_run[0] = l_run[0] * corr[0] + pl[0];
        l_run[1] = l_run[1] * corr[1] + pl[1];
        m_run[0] = mnew[0]; m_run[1] = mnew[1];

        // rescale O, then O += P @ V
#pragma unroll
        for (int nt = 0; nt < 16; nt++) {
            o[nt][0] *= corr[0]; o[nt][1] *= corr[0];
            o[nt][2] *= corr[1]; o[nt][3] *= corr[1];
        }
#pragma unroll
        for (int kk2 = 0; kk2 < 4; kk2++) {
#pragma unroll
            for (int etp = 0; etp < 8; etp++) {
                int row = kk2 * 16 + ((lane >> 3) & 1) * 8 + (lane & 7);
                int ch  = etp * 2 + (lane >> 4);
                int sc  = ((ch & 7) ^ (row & 7)) | (ch & 8);
                uint32_t r0, r1, r2, r3;
                ldsm_x4_t(r0, r1, r2, r3, Vb + row * 256 + sc * 16);
                mma_16816(o[2*etp],   pa[kk2], r0, r1);
                mma_16816(o[2*etp+1], pa[kk2], r2, r3);
            }
        }
    }

    // write normalized O
    float inv0 = 1.f / l_run[0], inv1 = 1.f / l_run[1];
    const int tg = t0 + wid * 16 + (lane >> 2);
    size_t base0 = ((size_t)b * T_ + tg)     * D_ + h * HD_;
    size_t base1 = ((size_t)b * T_ + tg + 8) * D_ + h * HD_;
#pragma unroll
    for (int nt = 0; nt < 16; nt++) {
        int e = nt * 8 + ((lane & 3) << 1);
        *(__half2*)(g_att + base0 + e) = __floats2half2_rn(o[nt][0] * inv0, o[nt][1] * inv0);
        *(__half2*)(g_att + base1 + e) = __floats2half2_rn(o[nt][2] * inv1, o[nt][3] * inv1);
    }
}

// ------------------------------------------------------------------
// Launch
// ------------------------------------------------------------------
extern "C" void kernel_launch(void* const* d_in, const int* in_sizes, int n_in,
                              void* d_out, int out_size) {
    const float* x   = (const float*)d_in[0];
    const float* Wq  = (const float*)d_in[1];
    const float* bq  = (const float*)d_in[2];
    const float* Wk  = (const float*)d_in[3];
    const float* bk  = (const float*)d_in[4];
    const float* Wv  = (const float*)d_in[5];
    const float* bv  = (const float*)d_in[6];
    const float* W1  = (const float*)d_in[7];
    const float* b1  = (const float*)d_in[8];
    const float* W2  = (const float*)d_in[9];
    const float* b2  = (const float*)d_in[10];
    const float* g1  = (const float*)d_in[11];
    const float* be1 = (const float*)d_in[12];
    const float* g2  = (const float*)d_in[13];
    const float* be2 = (const float*)d_in[14];
    float* out = (float*)d_out;

    __half *pWq, *pWk, *pWv, *pW1, *pW2, *pH, *pH2;
    cudaGetSymbolAddress((void**)&pWq, g_Wq);
    cudaGetSymbolAddress((void**)&pWk, g_Wk);
    cudaGetSymbolAddress((void**)&pWv, g_Wv);
    cudaGetSymbolAddress((void**)&pW1, g_W1);
    cudaGetSymbolAddress((void**)&pW2, g_W2);
    cudaGetSymbolAddress((void**)&pH,  g_h);
    cudaGetSymbolAddress((void**)&pH2, g_h2);

    const int nW  = H_ * D_ * HD_;   // 4,194,304
    const int nW1 = D_ * DFF_;       // 16,777,216

    f2h_kernel<<<(nW/8)  / 256, 256>>>((const float4*)Wq, (uint4*)pWq, nW/8);
    f2h_kernel<<<(nW/8)  / 256, 256>>>((const float4*)Wk, (uint4*)pWk, nW/8);
    f2h_kernel<<<(nW/8)  / 256, 256>>>((const float4*)Wv, (uint4*)pWv, nW/8);
    f2h_kernel<<<(nW1/8) / 256, 256>>>((const float4*)W1, (uint4*)pW1, nW1/8);
    f2h_kernel<<<(nW1/8) / 256, 256>>>((const float4*)W2, (uint4*)pW2, nW1/8);

    ln_kernel<<<R_, 256>>>(x, g1, be1, pH);

    cudaFuncSetAttribute(gemm_kernel, cudaFuncAttributeMaxDynamicSharedMemorySize, GSMEM);
    cudaFuncSetAttribute(attn_kernel, cudaFuncAttributeMaxDynamicSharedMemorySize, ASMEM);

    // QKV: N = 3*2048 = 6144
    gemm_kernel<<<dim3(6144 / BN, R_ / BM), 256, GSMEM>>>(0, bq, bk, bv, b1, b2, out);

    attn_kernel<<<dim3(T_ / AQ, B_ * H_), 256, ASMEM>>>();

    resid_ln_kernel<<<R_, 256>>>(x, g2, be2, out, pH2);

    gemm_kernel<<<dim3(DFF_ / BN, R_ / BM), 256, GSMEM>>>(1, bq, bk, bv, b1, b2, out);

    gemm_kernel<<<dim3(D_ / BN, R_ / BM), 256, GSMEM>>>(2, bq, bk, bv, b1, b2, out);
}

// round 5
// speedup vs baseline: 1.0381x; 1.0381x over previous
#include <cuda_runtime.h>
#include <cuda_fp16.h>
#include <cstdint>

// Problem constants
#define B_   4
#define T_   2048
#define D_   2048
#define H_   16
#define HD_  128
#define DFF_ 8192
#define R_   (B_*T_)      // 8192 rows

// ------------------------------------------------------------------
// Device scratch
// ------------------------------------------------------------------
__device__ __align__(256) __half g_h  [(size_t)R_*D_];
__device__ __align__(256) __half g_h2 [(size_t)R_*D_];
__device__ __align__(256) __half g_Wq [(size_t)H_*D_*HD_];
__device__ __align__(256) __half g_Wk [(size_t)H_*D_*HD_];
__device__ __align__(256) __half g_Wv [(size_t)H_*D_*HD_];
__device__ __align__(256) __half g_W1 [(size_t)D_*DFF_];
__device__ __align__(256) __half g_W2 [(size_t)DFF_*D_];
__device__ __align__(256) __half g_q  [(size_t)B_*H_*T_*HD_];
__device__ __align__(256) __half g_k  [(size_t)B_*H_*T_*HD_];
__device__ __align__(256) __half g_v  [(size_t)B_*H_*T_*HD_];
__device__ __align__(256) __half g_att[(size_t)R_*D_];
__device__ __align__(256) __half g_ff [(size_t)R_*DFF_];

// ------------------------------------------------------------------
// Helpers
// ------------------------------------------------------------------
__device__ __forceinline__ uint32_t smem_u32(const void* p) {
    return (uint32_t)__cvta_generic_to_shared(p);
}
__device__ __forceinline__ void cp16(uint32_t dst, const void* src) {
    asm volatile("cp.async.cg.shared.global [%0], [%1], 16;" :: "r"(dst), "l"(src));
}
#define CP_COMMIT() asm volatile("cp.async.commit_group;")
#define CP_WAIT0()  asm volatile("cp.async.wait_group 0;")
#define CP_WAIT1()  asm volatile("cp.async.wait_group 1;")

__device__ __forceinline__ void ldsm_x4(uint32_t& r0, uint32_t& r1, uint32_t& r2, uint32_t& r3, uint32_t a) {
    asm volatile("ldmatrix.sync.aligned.m8n8.x4.shared.b16 {%0,%1,%2,%3}, [%4];"
                 : "=r"(r0), "=r"(r1), "=r"(r2), "=r"(r3) : "r"(a));
}
__device__ __forceinline__ void ldsm_x4_t(uint32_t& r0, uint32_t& r1, uint32_t& r2, uint32_t& r3, uint32_t a) {
    asm volatile("ldmatrix.sync.aligned.m8n8.x4.trans.shared.b16 {%0,%1,%2,%3}, [%4];"
                 : "=r"(r0), "=r"(r1), "=r"(r2), "=r"(r3) : "r"(a));
}
__device__ __forceinline__ void mma_16816(float* c, const uint32_t* a, uint32_t b0, uint32_t b1v) {
    asm volatile(
        "mma.sync.aligned.m16n8k16.row.col.f32.f16.f16.f32 "
        "{%0,%1,%2,%3}, {%4,%5,%6,%7}, {%8,%9}, {%0,%1,%2,%3};\n"
        : "+f"(c[0]), "+f"(c[1]), "+f"(c[2]), "+f"(c[3])
        : "r"(a[0]), "r"(a[1]), "r"(a[2]), "r"(a[3]), "r"(b0), "r"(b1v));
}
__device__ __forceinline__ uint32_t packh2(float a, float b) {
    __half2 h = __floats2half2_rn(a, b);
    return *reinterpret_cast<uint32_t*>(&h);
}

// ------------------------------------------------------------------
// fp32 -> fp16 conversion, 8 elems/thread
// ------------------------------------------------------------------
__global__ void f2h_kernel(const float4* __restrict__ src, uint4* __restrict__ dst, int n8) {
    int i = blockIdx.x * blockDim.x + threadIdx.x;
    if (i >= n8) return;
    float4 a = src[2*i], b = src[2*i + 1];
    __half2 h0 = __floats2half2_rn(a.x, a.y);
    __half2 h1 = __floats2half2_rn(a.z, a.w);
    __half2 h2 = __floats2half2_rn(b.x, b.y);
    __half2 h3 = __floats2half2_rn(b.z, b.w);
    uint4 o;
    o.x = *(uint32_t*)&h0; o.y = *(uint32_t*)&h1;
    o.z = *(uint32_t*)&h2; o.w = *(uint32_t*)&h3;
    dst[i] = o;
}

// ------------------------------------------------------------------
// LayerNorm (block per row of D_=2048, 256 threads)
// ------------------------------------------------------------------
__global__ void __launch_bounds__(256) ln_kernel(
    const float* __restrict__ x, const float* __restrict__ g,
    const float* __restrict__ b, __half* __restrict__ out)
{
    int r = blockIdx.x;
    size_t off = (size_t)r * D_;
    float v[8], s = 0.f, s2 = 0.f;
#pragma unroll
    for (int j = 0; j < 8; j++) {
        float val = x[off + threadIdx.x + j*256];
        v[j] = val; s += val; s2 += val*val;
    }
    __shared__ float red[32];
#pragma unroll
    for (int o = 16; o; o >>= 1) { s += __shfl_xor_sync(~0u, s, o); s2 += __shfl_xor_sync(~0u, s2, o); }
    int wid = threadIdx.x >> 5;
    if ((threadIdx.x & 31) == 0) { red[wid] = s; red[8 + wid] = s2; }
    __syncthreads();
    if (threadIdx.x < 32) {
        float a  = (threadIdx.x < 8) ? red[threadIdx.x]   : 0.f;
        float c2 = (threadIdx.x < 8) ? red[8+threadIdx.x] : 0.f;
#pragma unroll
        for (int o = 4; o; o >>= 1) { a += __shfl_xor_sync(~0u, a, o); c2 += __shfl_xor_sync(~0u, c2, o); }
        if (threadIdx.x == 0) { red[16] = a; red[17] = c2; }
    }
    __syncthreads();
    float mu  = red[16] * (1.f / D_);
    float var = red[17] * (1.f / D_) - mu * mu;
    float rs  = rsqrtf(var + 1e-5f);
#pragma unroll
    for (int j = 0; j < 8; j++) {
        int c = threadIdx.x + j*256;
        out[off + c] = __float2half((v[j] - mu) * rs * g[c] + b[c]);
    }
}

// Fused: x1 = x + att ; write x1 to xout (fp32) ; h2 = LN(x1)
__global__ void __launch_bounds__(256) resid_ln_kernel(
    const float* __restrict__ x, const float* __restrict__ g,
    const float* __restrict__ b, float* __restrict__ xout,
    __half* __restrict__ h2)
{
    int r = blockIdx.x;
    size_t off = (size_t)r * D_;
    float v[8], s = 0.f, s2 = 0.f;
#pragma unroll
    for (int j = 0; j < 8; j++) {
        int c = threadIdx.x + j*256;
        float val = x[off + c] + __half2float(g_att[off + c]);
        xout[off + c] = val;
        v[j] = val; s += val; s2 += val*val;
    }
    __shared__ float red[32];
#pragma unroll
    for (int o = 16; o; o >>= 1) { s += __shfl_xor_sync(~0u, s, o); s2 += __shfl_xor_sync(~0u, s2, o); }
    int wid = threadIdx.x >> 5;
    if ((threadIdx.x & 31) == 0) { red[wid] = s; red[8 + wid] = s2; }
    __syncthreads();
    if (threadIdx.x < 32) {
        float a  = (threadIdx.x < 8) ? red[threadIdx.x]   : 0.f;
        float c2 = (threadIdx.x < 8) ? red[8+threadIdx.x] : 0.f;
#pragma unroll
        for (int o = 4; o; o >>= 1) { a += __shfl_xor_sync(~0u, a, o); c2 += __shfl_xor_sync(~0u, c2, o); }
        if (threadIdx.x == 0) { red[16] = a; red[17] = c2; }
    }
    __syncthreads();
    float mu  = red[16] * (1.f / D_);
    float var = red[17] * (1.f / D_) - mu * mu;
    float rs  = rsqrtf(var + 1e-5f);
#pragma unroll
    for (int j = 0; j < 8; j++) {
        int c = threadIdx.x + j*256;
        h2[off + c] = __float2half((v[j] - mu) * rs * g[c] + b[c]);
    }
}

// ------------------------------------------------------------------
// GEMM: C[M,N] = A[M,K]*B[K,N], 3-stage cp.async, ldmatrix, swizzled.
// BM=256, BN=128, BK=64; 512 threads (4x4 warps), warp tile 64x32.
// One __syncthreads per k-tile.
//   mode 0: QKV   mode 1: FFN1 (relu)   mode 2: FFN2 (xout += C + b2)
// ------------------------------------------------------------------
#define BM 256
#define BN 128
#define BK 64
#define ASTG (BM*BK*2)            // 32768 B
#define BSTG (BK*BN*2)            // 16384 B
#define STG  (ASTG + BSTG)        // 49152 B
#define GSMEM (3*STG)             // 147456 B

__global__ void __launch_bounds__(512, 1) gemm_kernel(
    int mode,
    const float* __restrict__ bq, const float* __restrict__ bk, const float* __restrict__ bv,
    const float* __restrict__ b1, const float* __restrict__ b2,
    float* __restrict__ xout)
{
    const __half* A; int K;
    if (mode == 0)      { A = g_h;  K = D_;   }
    else if (mode == 1) { A = g_h2; K = D_;   }
    else                { A = g_ff; K = DFF_; }

    const int m0 = blockIdx.y * BM;
    const int n0 = blockIdx.x * BN;
    const int nkt = K / BK;

    extern __shared__ __half dsm[];
    const uint32_t sbase = smem_u32(dsm);

    const int tid  = threadIdx.x;
    const int wid  = tid >> 5;
    const int lane = tid & 31;
    const int wm   = wid & 3;               // 0..3 (M quarter, 64 rows)
    const int wn   = wid >> 2;              // 0..3 (N quarter, 32 cols)

    float acc[4][4][4];
#pragma unroll
    for (int i = 0; i < 4; i++)
#pragma unroll
        for (int j = 0; j < 4; j++)
#pragma unroll
            for (int q = 0; q < 4; q++) acc[i][j][q] = 0.f;

    // ---- stage loader ----
    auto loadStage = [&](int kt, int s) {
        uint32_t sA = sbase + s * STG;
        uint32_t sB = sA + ASTG;
        // A: 256x64 -> 2048 chunks of 8 half; 4 per thread
#pragma unroll
        for (int i = 0; i < 4; i++) {
            int idx = tid + i * 512;
            int r = idx >> 3, c = idx & 7;
            int sc = c ^ (r & 7);
            cp16(sA + r * 128 + sc * 16, A + (size_t)(m0 + r) * K + kt * BK + c * 8);
        }
        // B: 64x128 -> 1024 chunks; 2 per thread
#pragma unroll
        for (int i = 0; i < 2; i++) {
            int idx = tid + i * 512;
            int r = idx >> 4, c = idx & 15;
            int sc = ((c & 7) ^ (r & 7)) | (c & 8);
            int n = n0 + c * 8;
            const __half* src;
            if (mode == 0) {
                int which = n >> 11, head = (n >> 7) & 15, e = n & 127;
                const __half* W = (which == 0) ? g_Wq : (which == 1) ? g_Wk : g_Wv;
                src = W + (size_t)head * (D_ * HD_) + (size_t)(kt * BK + r) * HD_ + e;
            } else if (mode == 1) {
                src = g_W1 + (size_t)(kt * BK + r) * DFF_ + n;
            } else {
                src = g_W2 + (size_t)(kt * BK + r) * D_ + n;
            }
            cp16(sB + r * 256 + sc * 16, src);
        }
    };

    loadStage(0, 0); CP_COMMIT();
    loadStage(1, 1); CP_COMMIT();

    for (int kt = 0; kt < nkt; kt++) {
        if (kt + 1 < nkt) { CP_WAIT1(); } else { CP_WAIT0(); }
        __syncthreads();
        // prefetch into the buffer drained by the barrier above
        if (kt + 2 < nkt) { loadStage(kt + 2, (kt + 2) % 3); CP_COMMIT(); }

        uint32_t sA = sbase + (kt % 3) * STG;
        uint32_t sB = sA + ASTG;

#pragma unroll
        for (int kk = 0; kk < 4; kk++) {
            uint32_t a[4][4];
#pragma unroll
            for (int mt = 0; mt < 4; mt++) {
                int row = wm * 64 + mt * 16 + (lane & 15);
                int ch  = 2 * kk + (lane >> 4);
                ldsm_x4(a[mt][0], a[mt][1], a[mt][2], a[mt][3],
                        sA + row * 128 + ((ch ^ (row & 7)) << 4));
            }
            uint32_t bf[4][2];
#pragma unroll
            for (int ntp = 0; ntp < 2; ntp++) {
                int row = kk * 16 + ((lane >> 3) & 1) * 8 + (lane & 7);
                int ch  = wn * 4 + ntp * 2 + (lane >> 4);
                int sc  = ((ch & 7) ^ (row & 7)) | (ch & 8);
                ldsm_x4_t(bf[2*ntp][0], bf[2*ntp][1], bf[2*ntp+1][0], bf[2*ntp+1][1],
                          sB + row * 256 + sc * 16);
            }
#pragma unroll
            for (int nt = 0; nt < 4; nt++)
#pragma unroll
                for (int mt = 0; mt < 4; mt++)
                    mma_16816(acc[mt][nt], a[mt], bf[nt][0], bf[nt][1]);
        }
    }

    // ---- Epilogue ----
    if (mode == 0) {
        int which = n0 >> 11, head = (n0 >> 7) & 15;
        const float* bias = ((which == 0) ? bq : (which == 1) ? bk : bv) + head * HD_;
        __half* qkv = (which == 0) ? g_q : (which == 1) ? g_k : g_v;
#pragma unroll
        for (int mt = 0; mt < 4; mt++) {
#pragma unroll
            for (int nt = 0; nt < 4; nt++) {
                float* cc = acc[mt][nt];
                int row0 = m0 + wm * 64 + mt * 16 + (lane >> 2);
                int e    = wn * 32 + nt * 8 + ((lane & 3) << 1);
                float bb0 = bias[e], bb1 = bias[e + 1];
#pragma unroll
                for (int rr = 0; rr < 2; rr++) {
                    int row = row0 + rr * 8;
                    int bb = row >> 11, t = row & (T_ - 1);
                    __half* dst = qkv + (((size_t)(bb * H_ + head) * T_ + t) * HD_) + e;
                    *(__half2*)dst = __floats2half2_rn(cc[rr*2] + bb0, cc[rr*2+1] + bb1);
                }
            }
        }
    } else if (mode == 1) {
#pragma unroll
        for (int mt = 0; mt < 4; mt++) {
#pragma unroll
            for (int nt = 0; nt < 4; nt++) {
                float* cc = acc[mt][nt];
                int row0 = m0 + wm * 64 + mt * 16 + (lane >> 2);
                int col  = n0 + wn * 32 + nt * 8 + ((lane & 3) << 1);
                float bb0 = b1[col], bb1 = b1[col + 1];
#pragma unroll
                for (int rr = 0; rr < 2; rr++) {
                    int row = row0 + rr * 8;
                    float v0 = fmaxf(cc[rr*2]   + bb0, 0.f);
                    float v1 = fmaxf(cc[rr*2+1] + bb1, 0.f);
                    *(__half2*)(g_ff + (size_t)row * DFF_ + col) = __floats2half2_rn(v0, v1);
                }
            }
        }
    } else {
#pragma unroll
        for (int mt = 0; mt < 4; mt++) {
#pragma unroll
            for (int nt = 0; nt < 4; nt++) {
                float* cc = acc[mt][nt];
                int row0 = m0 + wm * 64 + mt * 16 + (lane >> 2);
                int col  = n0 + wn * 32 + nt * 8 + ((lane & 3) << 1);
                float bb0 = b2[col], bb1 = b2[col + 1];
#pragma unroll
                for (int rr = 0; rr < 2; rr++) {
                    int row = row0 + rr * 8;
                    float2* d = (float2*)(xout + (size_t)row * D_ + col);
                    float2 val = *d;
                    val.x += cc[rr*2]   + bb0;
                    val.y += cc[rr*2+1] + bb1;
                    *d = val;
                }
            }
        }
    }
}

// ------------------------------------------------------------------
// Flash attention: grid (T/64, B*H), 128 threads (4 warps x 16 q rows)
// Double-buffered cp.async K/V (2 x 32KB dynamic smem).
// ------------------------------------------------------------------
#define AQ 64
#define AK 64
#define AKVSTG (AK*HD_*2)          // 16384 B per tensor per stage
#define ASMEM  (4*AKVSTG)          // 65536 B

__global__ void __launch_bounds__(128) attn_kernel() {
    const int bh = blockIdx.y;
    const int b  = bh >> 4, h = bh & 15;
    const int t0 = blockIdx.x * AQ;

    const __half* qbase = g_q + (size_t)bh * T_ * HD_;
    const __half* kbase = g_k + (size_t)bh * T_ * HD_;
    const __half* vbase = g_v + (size_t)bh * T_ * HD_;

    extern __shared__ __half kvsm[];
    const uint32_t kvbase = smem_u32(kvsm);

    const int tid  = threadIdx.x;
    const int wid  = tid >> 5;
    const int lane = tid & 31;
    const int qr   = wid * 16 + (lane >> 2);

    // Q fragments in registers
    uint32_t qa[8][4];
    {
        const __half* qp = qbase + (size_t)t0 * HD_;
#pragma unroll
        for (int kk = 0; kk < 8; kk++) {
            int c = ((lane & 3) << 1) + kk * 16;
            qa[kk][0] = *(const uint32_t*)(qp + (size_t)qr       * HD_ + c);
            qa[kk][1] = *(const uint32_t*)(qp + (size_t)(qr + 8) * HD_ + c);
            qa[kk][2] = *(const uint32_t*)(qp + (size_t)qr       * HD_ + c + 8);
            qa[kk][3] = *(const uint32_t*)(qp + (size_t)(qr + 8) * HD_ + c + 8);
        }
    }

    float m_run[2] = {-1e30f, -1e30f};
    float l_run[2] = {0.f, 0.f};
    float o[16][4];
#pragma unroll
    for (int i = 0; i < 16; i++)
#pragma unroll
        for (int q = 0; q < 4; q++) o[i][q] = 0.f;

    const float scale = 0.08838834764831845f;
    const int jmax = t0 / AK;

    auto loadKV = [&](int j, int s) {
        uint32_t kb = kvbase + s * (2 * AKVSTG);
        uint32_t vb = kb + AKVSTG;
        const __half* ks = kbase + (size_t)(j * AK) * HD_;
        const __half* vs = vbase + (size_t)(j * AK) * HD_;
#pragma unroll
        for (int i = 0; i < 8; i++) {
            int idx = tid + i * 128;
            int row = idx >> 4, ch = idx & 15;
            int sc = ((ch & 7) ^ (row & 7)) | (ch & 8);
            cp16(kb + row * 256 + sc * 16, ks + (size_t)row * HD_ + ch * 8);
            cp16(vb + row * 256 + sc * 16, vs + (size_t)row * HD_ + ch * 8);
        }
    };

    loadKV(0, 0); CP_COMMIT();

    for (int j = 0; j <= jmax; j++) {
        const int s0 = j * AK;
        __syncthreads();   // prior compute done before next prefetch overwrites
        if (j + 1 <= jmax) { loadKV(j + 1, (j + 1) & 1); CP_COMMIT(); CP_WAIT1(); }
        else               { CP_WAIT0(); }
        __syncthreads();   // visibility of this tile's data

        uint32_t Kb = kvbase + (j & 1) * (2 * AKVSTG);
        uint32_t Vb = Kb + AKVSTG;

        // S = Q K^T
        float sacc[8][4];
#pragma unroll
        for (int nt = 0; nt < 8; nt++)
#pragma unroll
            for (int q = 0; q < 4; q++) sacc[nt][q] = 0.f;

#pragma unroll
        for (int kk = 0; kk < 8; kk++) {
#pragma unroll
            for (int ntp = 0; ntp < 4; ntp++) {
                int row = ntp * 16 + ((lane >> 4) << 3) + (lane & 7);
                int ch  = 2 * kk + ((lane >> 3) & 1);
                int sc  = ((ch & 7) ^ (row & 7)) | (ch & 8);
                uint32_t r0, r1, r2, r3;
                ldsm_x4(r0, r1, r2, r3, Kb + row * 256 + sc * 16);
                mma_16816(sacc[2*ntp],   qa[kk], r0, r1);
                mma_16816(sacc[2*ntp+1], qa[kk], r2, r3);
            }
        }

        // scale + causal mask + tile max
        const int tg0 = t0 + wid * 16 + (lane >> 2);
        float mtile[2] = {-1e30f, -1e30f};
#pragma unroll
        for (int nt = 0; nt < 8; nt++) {
            int sg = s0 + nt * 8 + ((lane & 3) << 1);
#pragma unroll
            for (int q = 0; q < 4; q++) {
                int rsel = q >> 1;
                int scol = sg + (q & 1);
                int tg   = tg0 + (rsel ? 8 : 0);
                float vv = sacc[nt][q] * scale;
                if (scol > tg) vv = -1e30f;
                sacc[nt][q] = vv;
                mtile[rsel] = fmaxf(mtile[rsel], vv);
            }
        }
#pragma unroll
        for (int o2 = 1; o2 < 4; o2 <<= 1) {
            mtile[0] = fmaxf(mtile[0], __shfl_xor_sync(~0u, mtile[0], o2));
            mtile[1] = fmaxf(mtile[1], __shfl_xor_sync(~0u, mtile[1], o2));
        }
        float mnew[2] = {fmaxf(m_run[0], mtile[0]), fmaxf(m_run[1], mtile[1])};
        float corr[2] = {__expf(m_run[0] - mnew[0]), __expf(m_run[1] - mnew[1])};

        // P = exp(S - m)
        float pl[2] = {0.f, 0.f};
        uint32_t pa[4][4];
#pragma unroll
        for (int nt = 0; nt < 8; nt++) {
            float p0 = __expf(sacc[nt][0] - mnew[0]);
            float p1 = __expf(sacc[nt][1] - mnew[0]);
            float p2 = __expf(sacc[nt][2] - mnew[1]);
            float p3 = __expf(sacc[nt][3] - mnew[1]);
            pl[0] += p0 + p1; pl[1] += p2 + p3;
            int kk2 = nt >> 1, hi = nt & 1;
            pa[kk2][2*hi]     = packh2(p0, p1);
            pa[kk2][2*hi + 1] = packh2(p2, p3);
        }
#pragma unroll
        for (int o2 = 1; o2 < 4; o2 <<= 1) {
            pl[0] += __shfl_xor_sync(~0u, pl[0], o2);
            pl[1] += __shfl_xor_sync(~0u, pl[1], o2);
        }
        l_run[0] = l_run[0] * corr[0] + pl[0];
        l_run[1] = l_run[1] * corr[1] + pl[1];
        m_run[0] = mnew[0]; m_run[1] = mnew[1];

        // rescale O, then O += P @ V
#pragma unroll
        for (int nt = 0; nt < 16; nt++) {
            o[nt][0] *= corr[0]; o[nt][1] *= corr[0];
            o[nt][2] *= corr[1]; o[nt][3] *= corr[1];
        }
#pragma unroll
        for (int kk2 = 0; kk2 < 4; kk2++) {
#pragma unroll
            for (int etp = 0; etp < 8; etp++) {
                int row = kk2 * 16 + ((lane >> 3) & 1) * 8 + (lane & 7);
                int ch  = etp * 2 + (lane >> 4);
                int sc  = ((ch & 7) ^ (row & 7)) | (ch & 8);
                uint32_t r0, r1, r2, r3;
                ldsm_x4_t(r0, r1, r2, r3, Vb + row * 256 + sc * 16);
                mma_16816(o[2*etp],   pa[kk2], r0, r1);
                mma_16816(o[2*etp+1], pa[kk2], r2, r3);
            }
        }
    }

    // write normalized O
    float inv0 = 1.f / l_run[0], inv1 = 1.f / l_run[1];
    const int tg = t0 + wid * 16 + (lane >> 2);
    size_t base0 = ((size_t)b * T_ + tg)     * D_ + h * HD_;
    size_t base1 = ((size_t)b * T_ + tg + 8) * D_ + h * HD_;
#pragma unroll
    for (int nt = 0; nt < 16; nt++) {
        int e = nt * 8 + ((lane & 3) << 1);
        *(__half2*)(g_att + base0 + e) = __floats2half2_rn(o[nt][0] * inv0, o[nt][1] * inv0);
        *(__half2*)(g_att + base1 + e) = __floats2half2_rn(o[nt][2] * inv1, o[nt][3] * inv1);
    }
}

// ------------------------------------------------------------------
// Launch
// ------------------------------------------------------------------
extern "C" void kernel_launch(void* const* d_in, const int* in_sizes, int n_in,
                              void* d_out, int out_size) {
    const float* x   = (const float*)d_in[0];
    const float* Wq  = (const float*)d_in[1];
    const float* bq  = (const float*)d_in[2];
    const float* Wk  = (const float*)d_in[3];
    const float* bk  = (const float*)d_in[4];
    const float* Wv  = (const float*)d_in[5];
    const float* bv  = (const float*)d_in[6];
    const float* W1  = (const float*)d_in[7];
    const float* b1  = (const float*)d_in[8];
    const float* W2  = (const float*)d_in[9];
    const float* b2  = (const float*)d_in[10];
    const float* g1  = (const float*)d_in[11];
    const float* be1 = (const float*)d_in[12];
    const float* g2  = (const float*)d_in[13];
    const float* be2 = (const float*)d_in[14];
    float* out = (float*)d_out;

    __half *pWq, *pWk, *pWv, *pW1, *pW2, *pH, *pH2;
    cudaGetSymbolAddress((void**)&pWq, g_Wq);
    cudaGetSymbolAddress((void**)&pWk, g_Wk);
    cudaGetSymbolAddress((void**)&pWv, g_Wv);
    cudaGetSymbolAddress((void**)&pW1, g_W1);
    cudaGetSymbolAddress((void**)&pW2, g_W2);
    cudaGetSymbolAddress((void**)&pH,  g_h);
    cudaGetSymbolAddress((void**)&pH2, g_h2);

    const int nW  = H_ * D_ * HD_;   // 4,194,304
    const int nW1 = D_ * DFF_;       // 16,777,216

    f2h_kernel<<<(nW/8)  / 256, 256>>>((const float4*)Wq, (uint4*)pWq, nW/8);
    f2h_kernel<<<(nW/8)  / 256, 256>>>((const float4*)Wk, (uint4*)pWk, nW/8);
    f2h_kernel<<<(nW/8)  / 256, 256>>>((const float4*)Wv, (uint4*)pWv, nW/8);
    f2h_kernel<<<(nW1/8) / 256, 256>>>((const float4*)W1, (uint4*)pW1, nW1/8);
    f2h_kernel<<<(nW1/8) / 256, 256>>>((const float4*)W2, (uint4*)pW2, nW1/8);

    ln_kernel<<<R_, 256>>>(x, g1, be1, pH);

    cudaFuncSetAttribute(gemm_kernel, cudaFuncAttributeMaxDynamicSharedMemorySize, GSMEM);
    cudaFuncSetAttribute(attn_kernel, cudaFuncAttributeMaxDynamicSharedMemorySize, ASMEM);

    // QKV: N = 3*2048 = 6144
    gemm_kernel<<<dim3(6144 / BN, R_ / BM), 512, GSMEM>>>(0, bq, bk, bv, b1, b2, out);

    attn_kernel<<<dim3(T_ / AQ, B_ * H_), 128, ASMEM>>>();

    resid_ln_kernel<<<R_, 256>>>(x, g2, be2, out, pH2);

    gemm_kernel<<<dim3(DFF_ / BN, R_ / BM), 512, GSMEM>>>(1, bq, bk, bv, b1, b2, out);

    gemm_kernel<<<dim3(D_ / BN, R_ / BM), 512, GSMEM>>>(2, bq, bk, bv, b1, b2, out);
}

// round 6
// speedup vs baseline: 1.1290x; 1.0876x over previous
#include <cuda_runtime.h>
#include <cuda_fp16.h>
#include <cstdint>

// Problem constants
#define B_   4
#define T_   2048
#define D_   2048
#define H_   16
#define HD_  128
#define DFF_ 8192
#define R_   (B_*T_)      // 8192 rows

// ------------------------------------------------------------------
// Device scratch
// ------------------------------------------------------------------
__device__ __align__(256) __half g_h  [(size_t)R_*D_];
__device__ __align__(256) __half g_h2 [(size_t)R_*D_];
__device__ __align__(256) __half g_Wq [(size_t)H_*D_*HD_];
__device__ __align__(256) __half g_Wk [(size_t)H_*D_*HD_];
__device__ __align__(256) __half g_Wv [(size_t)H_*D_*HD_];
__device__ __align__(256) __half g_W1 [(size_t)D_*DFF_];
__device__ __align__(256) __half g_W2 [(size_t)DFF_*D_];
__device__ __align__(256) __half g_q  [(size_t)B_*H_*T_*HD_];
__device__ __align__(256) __half g_k  [(size_t)B_*H_*T_*HD_];
__device__ __align__(256) __half g_v  [(size_t)B_*H_*T_*HD_];
__device__ __align__(256) __half g_att[(size_t)R_*D_];
__device__ __align__(256) __half g_ff [(size_t)R_*DFF_];

// ------------------------------------------------------------------
// Helpers
// ------------------------------------------------------------------
__device__ __forceinline__ uint32_t smem_u32(const void* p) {
    return (uint32_t)__cvta_generic_to_shared(p);
}
__device__ __forceinline__ void cp16(uint32_t dst, const void* src) {
    asm volatile("cp.async.cg.shared.global [%0], [%1], 16;" :: "r"(dst), "l"(src));
}
#define CP_COMMIT() asm volatile("cp.async.commit_group;")
#define CP_WAIT0()  asm volatile("cp.async.wait_group 0;")
#define CP_WAIT1()  asm volatile("cp.async.wait_group 1;")

__device__ __forceinline__ void ldsm_x4(uint32_t& r0, uint32_t& r1, uint32_t& r2, uint32_t& r3, uint32_t a) {
    asm volatile("ldmatrix.sync.aligned.m8n8.x4.shared.b16 {%0,%1,%2,%3}, [%4];"
                 : "=r"(r0), "=r"(r1), "=r"(r2), "=r"(r3) : "r"(a));
}
__device__ __forceinline__ void ldsm_x4_t(uint32_t& r0, uint32_t& r1, uint32_t& r2, uint32_t& r3, uint32_t a) {
    asm volatile("ldmatrix.sync.aligned.m8n8.x4.trans.shared.b16 {%0,%1,%2,%3}, [%4];"
                 : "=r"(r0), "=r"(r1), "=r"(r2), "=r"(r3) : "r"(a));
}
__device__ __forceinline__ void mma_16816(float* c, const uint32_t* a, uint32_t b0, uint32_t b1v) {
    asm volatile(
        "mma.sync.aligned.m16n8k16.row.col.f32.f16.f16.f32 "
        "{%0,%1,%2,%3}, {%4,%5,%6,%7}, {%8,%9}, {%0,%1,%2,%3};\n"
        : "+f"(c[0]), "+f"(c[1]), "+f"(c[2]), "+f"(c[3])
        : "r"(a[0]), "r"(a[1]), "r"(a[2]), "r"(a[3]), "r"(b0), "r"(b1v));
}
__device__ __forceinline__ uint32_t packh2(float a, float b) {
    __half2 h = __floats2half2_rn(a, b);
    return *reinterpret_cast<uint32_t*>(&h);
}

// ------------------------------------------------------------------
// fp32 -> fp16 conversion, 8 elems/thread
// ------------------------------------------------------------------
__global__ void f2h_kernel(const float4* __restrict__ src, uint4* __restrict__ dst, int n8) {
    int i = blockIdx.x * blockDim.x + threadIdx.x;
    if (i >= n8) return;
    float4 a = src[2*i], b = src[2*i + 1];
    __half2 h0 = __floats2half2_rn(a.x, a.y);
    __half2 h1 = __floats2half2_rn(a.z, a.w);
    __half2 h2 = __floats2half2_rn(b.x, b.y);
    __half2 h3 = __floats2half2_rn(b.z, b.w);
    uint4 o;
    o.x = *(uint32_t*)&h0; o.y = *(uint32_t*)&h1;
    o.z = *(uint32_t*)&h2; o.w = *(uint32_t*)&h3;
    dst[i] = o;
}

// ------------------------------------------------------------------
// LayerNorm (block per row of D_=2048, 256 threads)
// ------------------------------------------------------------------
__global__ void __launch_bounds__(256) ln_kernel(
    const float* __restrict__ x, const float* __restrict__ g,
    const float* __restrict__ b, __half* __restrict__ out)
{
    int r = blockIdx.x;
    size_t off = (size_t)r * D_;
    float v[8], s = 0.f, s2 = 0.f;
#pragma unroll
    for (int j = 0; j < 8; j++) {
        float val = x[off + threadIdx.x + j*256];
        v[j] = val; s += val; s2 += val*val;
    }
    __shared__ float red[32];
#pragma unroll
    for (int o = 16; o; o >>= 1) { s += __shfl_xor_sync(~0u, s, o); s2 += __shfl_xor_sync(~0u, s2, o); }
    int wid = threadIdx.x >> 5;
    if ((threadIdx.x & 31) == 0) { red[wid] = s; red[8 + wid] = s2; }
    __syncthreads();
    if (threadIdx.x < 32) {
        float a  = (threadIdx.x < 8) ? red[threadIdx.x]   : 0.f;
        float c2 = (threadIdx.x < 8) ? red[8+threadIdx.x] : 0.f;
#pragma unroll
        for (int o = 4; o; o >>= 1) { a += __shfl_xor_sync(~0u, a, o); c2 += __shfl_xor_sync(~0u, c2, o); }
        if (threadIdx.x == 0) { red[16] = a; red[17] = c2; }
    }
    __syncthreads();
    float mu  = red[16] * (1.f / D_);
    float var = red[17] * (1.f / D_) - mu * mu;
    float rs  = rsqrtf(var + 1e-5f);
#pragma unroll
    for (int j = 0; j < 8; j++) {
        int c = threadIdx.x + j*256;
        out[off + c] = __float2half((v[j] - mu) * rs * g[c] + b[c]);
    }
}

// Fused: x1 = x + att ; write x1 to xout (fp32) ; h2 = LN(x1)
__global__ void __launch_bounds__(256) resid_ln_kernel(
    const float* __restrict__ x, const float* __restrict__ g,
    const float* __restrict__ b, float* __restrict__ xout,
    __half* __restrict__ h2)
{
    int r = blockIdx.x;
    size_t off = (size_t)r * D_;
    float v[8], s = 0.f, s2 = 0.f;
#pragma unroll
    for (int j = 0; j < 8; j++) {
        int c = threadIdx.x + j*256;
        float val = x[off + c] + __half2float(g_att[off + c]);
        xout[off + c] = val;
        v[j] = val; s += val; s2 += val*val;
    }
    __shared__ float red[32];
#pragma unroll
    for (int o = 16; o; o >>= 1) { s += __shfl_xor_sync(~0u, s, o); s2 += __shfl_xor_sync(~0u, s2, o); }
    int wid = threadIdx.x >> 5;
    if ((threadIdx.x & 31) == 0) { red[wid] = s; red[8 + wid] = s2; }
    __syncthreads();
    if (threadIdx.x < 32) {
        float a  = (threadIdx.x < 8) ? red[threadIdx.x]   : 0.f;
        float c2 = (threadIdx.x < 8) ? red[8+threadIdx.x] : 0.f;
#pragma unroll
        for (int o = 4; o; o >>= 1) { a += __shfl_xor_sync(~0u, a, o); c2 += __shfl_xor_sync(~0u, c2, o); }
        if (threadIdx.x == 0) { red[16] = a; red[17] = c2; }
    }
    __syncthreads();
    float mu  = red[16] * (1.f / D_);
    float var = red[17] * (1.f / D_) - mu * mu;
    float rs  = rsqrtf(var + 1e-5f);
#pragma unroll
    for (int j = 0; j < 8; j++) {
        int c = threadIdx.x + j*256;
        h2[off + c] = __float2half((v[j] - mu) * rs * g[c] + b[c]);
    }
}

// ------------------------------------------------------------------
// GEMM: C[M,N] = A[M,K]*B[K,N], 3-stage cp.async, ldmatrix, swizzled.
// BM=128, BN=128, BK=64; 256 threads (2x4 warps), warp tile 64x32.
// 2 CTAs/SM, one __syncthreads per k-tile.
//   mode 0: QKV   mode 1: FFN1 (relu)   mode 2: FFN2 (xout += C + b2)
// ------------------------------------------------------------------
#define BM 128
#define BN 128
#define BK 64
#define ASTG (BM*BK*2)            // 16384 B
#define BSTG (BK*BN*2)            // 16384 B
#define STG  (ASTG + BSTG)        // 32768 B
#define GSMEM (3*STG)             // 98304 B

__global__ void __launch_bounds__(256, 2) gemm_kernel(
    int mode,
    const float* __restrict__ bq, const float* __restrict__ bk, const float* __restrict__ bv,
    const float* __restrict__ b1, const float* __restrict__ b2,
    float* __restrict__ xout)
{
    const __half* A; int K;
    if (mode == 0)      { A = g_h;  K = D_;   }
    else if (mode == 1) { A = g_h2; K = D_;   }
    else                { A = g_ff; K = DFF_; }

    const int m0 = blockIdx.y * BM;
    const int n0 = blockIdx.x * BN;
    const int nkt = K / BK;

    extern __shared__ __half dsm[];
    const uint32_t sbase = smem_u32(dsm);

    const int tid  = threadIdx.x;
    const int wid  = tid >> 5;
    const int lane = tid & 31;
    const int wm   = wid & 1;               // 0..1 (M half, 64 rows)
    const int wn   = wid >> 1;              // 0..3 (N quarter, 32 cols)

    float acc[4][4][4];
#pragma unroll
    for (int i = 0; i < 4; i++)
#pragma unroll
        for (int j = 0; j < 4; j++)
#pragma unroll
            for (int q = 0; q < 4; q++) acc[i][j][q] = 0.f;

    // ---- stage loader ----
    auto loadStage = [&](int kt, int s) {
        uint32_t sA = sbase + s * STG;
        uint32_t sB = sA + ASTG;
        // A: 128x64 -> 1024 chunks of 16B; 4 per thread
#pragma unroll
        for (int i = 0; i < 4; i++) {
            int idx = tid + i * 256;
            int r = idx >> 3, c = idx & 7;
            int sc = c ^ (r & 7);
            cp16(sA + r * 128 + sc * 16, A + (size_t)(m0 + r) * K + kt * BK + c * 8);
        }
        // B: 64x128 -> 1024 chunks; 4 per thread
#pragma unroll
        for (int i = 0; i < 4; i++) {
            int idx = tid + i * 256;
            int r = idx >> 4, c = idx & 15;
            int sc = ((c & 7) ^ (r & 7)) | (c & 8);
            int n = n0 + c * 8;
            const __half* src;
            if (mode == 0) {
                int which = n >> 11, head = (n >> 7) & 15, e = n & 127;
                const __half* W = (which == 0) ? g_Wq : (which == 1) ? g_Wk : g_Wv;
                src = W + (size_t)head * (D_ * HD_) + (size_t)(kt * BK + r) * HD_ + e;
            } else if (mode == 1) {
                src = g_W1 + (size_t)(kt * BK + r) * DFF_ + n;
            } else {
                src = g_W2 + (size_t)(kt * BK + r) * D_ + n;
            }
            cp16(sB + r * 256 + sc * 16, src);
        }
    };

    loadStage(0, 0); CP_COMMIT();
    loadStage(1, 1); CP_COMMIT();

    for (int kt = 0; kt < nkt; kt++) {
        if (kt + 1 < nkt) { CP_WAIT1(); } else { CP_WAIT0(); }
        __syncthreads();
        // prefetch into the stage drained by the barrier above (distance 2)
        if (kt + 2 < nkt) { loadStage(kt + 2, (kt + 2) % 3); CP_COMMIT(); }

        uint32_t sA = sbase + (kt % 3) * STG;
        uint32_t sB = sA + ASTG;

#pragma unroll
        for (int kk = 0; kk < 4; kk++) {
            uint32_t a[4][4];
#pragma unroll
            for (int mt = 0; mt < 4; mt++) {
                int row = wm * 64 + mt * 16 + (lane & 15);
                int ch  = 2 * kk + (lane >> 4);
                ldsm_x4(a[mt][0], a[mt][1], a[mt][2], a[mt][3],
                        sA + row * 128 + ((ch ^ (row & 7)) << 4));
            }
            uint32_t bf[4][2];
#pragma unroll
            for (int ntp = 0; ntp < 2; ntp++) {
                int row = kk * 16 + ((lane >> 3) & 1) * 8 + (lane & 7);
                int ch  = wn * 4 + ntp * 2 + (lane >> 4);
                int sc  = ((ch & 7) ^ (row & 7)) | (ch & 8);
                ldsm_x4_t(bf[2*ntp][0], bf[2*ntp][1], bf[2*ntp+1][0], bf[2*ntp+1][1],
                          sB + row * 256 + sc * 16);
            }
#pragma unroll
            for (int nt = 0; nt < 4; nt++)
#pragma unroll
                for (int mt = 0; mt < 4; mt++)
                    mma_16816(acc[mt][nt], a[mt], bf[nt][0], bf[nt][1]);
        }
    }

    // ---- Epilogue ----
    if (mode == 0) {
        int which = n0 >> 11, head = (n0 >> 7) & 15;
        const float* bias = ((which == 0) ? bq : (which == 1) ? bk : bv) + head * HD_;
        __half* qkv = (which == 0) ? g_q : (which == 1) ? g_k : g_v;
#pragma unroll
        for (int mt = 0; mt < 4; mt++) {
#pragma unroll
            for (int nt = 0; nt < 4; nt++) {
                float* cc = acc[mt][nt];
                int row0 = m0 + wm * 64 + mt * 16 + (lane >> 2);
                int e    = wn * 32 + nt * 8 + ((lane & 3) << 1);
                float bb0 = bias[e], bb1 = bias[e + 1];
#pragma unroll
                for (int rr = 0; rr < 2; rr++) {
                    int row = row0 + rr * 8;
                    int bb = row >> 11, t = row & (T_ - 1);
                    __half* dst = qkv + (((size_t)(bb * H_ + head) * T_ + t) * HD_) + e;
                    *(__half2*)dst = __floats2half2_rn(cc[rr*2] + bb0, cc[rr*2+1] + bb1);
                }
            }
        }
    } else if (mode == 1) {
#pragma unroll
        for (int mt = 0; mt < 4; mt++) {
#pragma unroll
            for (int nt = 0; nt < 4; nt++) {
                float* cc = acc[mt][nt];
                int row0 = m0 + wm * 64 + mt * 16 + (lane >> 2);
                int col  = n0 + wn * 32 + nt * 8 + ((lane & 3) << 1);
                float bb0 = b1[col], bb1 = b1[col + 1];
#pragma unroll
                for (int rr = 0; rr < 2; rr++) {
                    int row = row0 + rr * 8;
                    float v0 = fmaxf(cc[rr*2]   + bb0, 0.f);
                    float v1 = fmaxf(cc[rr*2+1] + bb1, 0.f);
                    *(__half2*)(g_ff + (size_t)row * DFF_ + col) = __floats2half2_rn(v0, v1);
                }
            }
        }
    } else {
#pragma unroll
        for (int mt = 0; mt < 4; mt++) {
#pragma unroll
            for (int nt = 0; nt < 4; nt++) {
                float* cc = acc[mt][nt];
                int row0 = m0 + wm * 64 + mt * 16 + (lane >> 2);
                int col  = n0 + wn * 32 + nt * 8 + ((lane & 3) << 1);
                float bb0 = b2[col], bb1 = b2[col + 1];
#pragma unroll
                for (int rr = 0; rr < 2; rr++) {
                    int row = row0 + rr * 8;
                    float2* d = (float2*)(xout + (size_t)row * D_ + col);
                    float2 val = *d;
                    val.x += cc[rr*2]   + bb0;
                    val.y += cc[rr*2+1] + bb1;
                    *d = val;
                }
            }
        }
    }
}

// ------------------------------------------------------------------
// Flash attention: grid (T/64, B*H), 128 threads (4 warps x 16 q rows)
// Double-buffered cp.async K/V (2 x 32KB dynamic smem).
// ------------------------------------------------------------------
#define AQ 64
#define AK 64
#define AKVSTG (AK*HD_*2)          // 16384 B per tensor per stage
#define ASMEM  (4*AKVSTG)          // 65536 B

__global__ void __launch_bounds__(128) attn_kernel() {
    const int bh = blockIdx.y;
    const int b  = bh >> 4, h = bh & 15;
    const int t0 = blockIdx.x * AQ;

    const __half* qbase = g_q + (size_t)bh * T_ * HD_;
    const __half* kbase = g_k + (size_t)bh * T_ * HD_;
    const __half* vbase = g_v + (size_t)bh * T_ * HD_;

    extern __shared__ __half kvsm[];
    const uint32_t kvbase = smem_u32(kvsm);

    const int tid  = threadIdx.x;
    const int wid  = tid >> 5;
    const int lane = tid & 31;
    const int qr   = wid * 16 + (lane >> 2);

    // Q fragments in registers
    uint32_t qa[8][4];
    {
        const __half* qp = qbase + (size_t)t0 * HD_;
#pragma unroll
        for (int kk = 0; kk < 8; kk++) {
            int c = ((lane & 3) << 1) + kk * 16;
            qa[kk][0] = *(const uint32_t*)(qp + (size_t)qr       * HD_ + c);
            qa[kk][1] = *(const uint32_t*)(qp + (size_t)(qr + 8) * HD_ + c);
            qa[kk][2] = *(const uint32_t*)(qp + (size_t)qr       * HD_ + c + 8);
            qa[kk][3] = *(const uint32_t*)(qp + (size_t)(qr + 8) * HD_ + c + 8);
        }
    }

    float m_run[2] = {-1e30f, -1e30f};
    float l_run[2] = {0.f, 0.f};
    float o[16][4];
#pragma unroll
    for (int i = 0; i < 16; i++)
#pragma unroll
        for (int q = 0; q < 4; q++) o[i][q] = 0.f;

    const float scale = 0.08838834764831845f;
    const int jmax = t0 / AK;

    auto loadKV = [&](int j, int s) {
        uint32_t kb = kvbase + s * (2 * AKVSTG);
        uint32_t vb = kb + AKVSTG;
        const __half* ks = kbase + (size_t)(j * AK) * HD_;
        const __half* vs = vbase + (size_t)(j * AK) * HD_;
#pragma unroll
        for (int i = 0; i < 8; i++) {
            int idx = tid + i * 128;
            int row = idx >> 4, ch = idx & 15;
            int sc = ((ch & 7) ^ (row & 7)) | (ch & 8);
            cp16(kb + row * 256 + sc * 16, ks + (size_t)row * HD_ + ch * 8);
            cp16(vb + row * 256 + sc * 16, vs + (size_t)row * HD_ + ch * 8);
        }
    };

    loadKV(0, 0); CP_COMMIT();

    for (int j = 0; j <= jmax; j++) {
        const int s0 = j * AK;
        __syncthreads();   // prior compute done before next prefetch overwrites
        if (j + 1 <= jmax) { loadKV(j + 1, (j + 1) & 1); CP_COMMIT(); CP_WAIT1(); }
        else               { CP_WAIT0(); }
        __syncthreads();   // visibility of this tile's data

        uint32_t Kb = kvbase + (j & 1) * (2 * AKVSTG);
        uint32_t Vb = Kb + AKVSTG;

        // S = Q K^T
        float sacc[8][4];
#pragma unroll
        for (int nt = 0; nt < 8; nt++)
#pragma unroll
            for (int q = 0; q < 4; q++) sacc[nt][q] = 0.f;

#pragma unroll
        for (int kk = 0; kk < 8; kk++) {
#pragma unroll
            for (int ntp = 0; ntp < 4; ntp++) {
                int row = ntp * 16 + ((lane >> 4) << 3) + (lane & 7);
                int ch  = 2 * kk + ((lane >> 3) & 1);
                int sc  = ((ch & 7) ^ (row & 7)) | (ch & 8);
                uint32_t r0, r1, r2, r3;
                ldsm_x4(r0, r1, r2, r3, Kb + row * 256 + sc * 16);
                mma_16816(sacc[2*ntp],   qa[kk], r0, r1);
                mma_16816(sacc[2*ntp+1], qa[kk], r2, r3);
            }
        }

        // scale + causal mask + tile max
        const int tg0 = t0 + wid * 16 + (lane >> 2);
        float mtile[2] = {-1e30f, -1e30f};
#pragma unroll
        for (int nt = 0; nt < 8; nt++) {
            int sg = s0 + nt * 8 + ((lane & 3) << 1);
#pragma unroll
            for (int q = 0; q < 4; q++) {
                int rsel = q >> 1;
                int scol = sg + (q & 1);
                int tg   = tg0 + (rsel ? 8 : 0);
                float vv = sacc[nt][q] * scale;
                if (scol > tg) vv = -1e30f;
                sacc[nt][q] = vv;
                mtile[rsel] = fmaxf(mtile[rsel], vv);
            }
        }
#pragma unroll
        for (int o2 = 1; o2 < 4; o2 <<= 1) {
            mtile[0] = fmaxf(mtile[0], __shfl_xor_sync(~0u, mtile[0], o2));
            mtile[1] = fmaxf(mtile[1], __shfl_xor_sync(~0u, mtile[1], o2));
        }
        float mnew[2] = {fmaxf(m_run[0], mtile[0]), fmaxf(m_run[1], mtile[1])};
        float corr[2] = {__expf(m_run[0] - mnew[0]), __expf(m_run[1] - mnew[1])};

        // P = exp(S - m)
        float pl[2] = {0.f, 0.f};
        uint32_t pa[4][4];
#pragma unroll
        for (int nt = 0; nt < 8; nt++) {
            float p0 = __expf(sacc[nt][0] - mnew[0]);
            float p1 = __expf(sacc[nt][1] - mnew[0]);
            float p2 = __expf(sacc[nt][2] - mnew[1]);
            float p3 = __expf(sacc[nt][3] - mnew[1]);
            pl[0] += p0 + p1; pl[1] += p2 + p3;
            int kk2 = nt >> 1, hi = nt & 1;
            pa[kk2][2*hi]     = packh2(p0, p1);
            pa[kk2][2*hi + 1] = packh2(p2, p3);
        }
#pragma unroll
        for (int o2 = 1; o2 < 4; o2 <<= 1) {
            pl[0] += __shfl_xor_sync(~0u, pl[0], o2);
            pl[1] += __shfl_xor_sync(~0u, pl[1], o2);
        }
        l_run[0] = l_run[0] * corr[0] + pl[0];
        l_run[1] = l_run[1] * corr[1] + pl[1];
        m_run[0] = mnew[0]; m_run[1] = mnew[1];

        // rescale O, then O += P @ V
#pragma unroll
        for (int nt = 0; nt < 16; nt++) {
            o[nt][0] *= corr[0]; o[nt][1] *= corr[0];
            o[nt][2] *= corr[1]; o[nt][3] *= corr[1];
        }
#pragma unroll
        for (int kk2 = 0; kk2 < 4; kk2++) {
#pragma unroll
            for (int etp = 0; etp < 8; etp++) {
                int row = kk2 * 16 + ((lane >> 3) & 1) * 8 + (lane & 7);
                int ch  = etp * 2 + (lane >> 4);
                int sc  = ((ch & 7) ^ (row & 7)) | (ch & 8);
                uint32_t r0, r1, r2, r3;
                ldsm_x4_t(r0, r1, r2, r3, Vb + row * 256 + sc * 16);
                mma_16816(o[2*etp],   pa[kk2], r0, r1);
                mma_16816(o[2*etp+1], pa[kk2], r2, r3);
            }
        }
    }

    // write normalized O
    float inv0 = 1.f / l_run[0], inv1 = 1.f / l_run[1];
    const int tg = t0 + wid * 16 + (lane >> 2);
    size_t base0 = ((size_t)b * T_ + tg)     * D_ + h * HD_;
    size_t base1 = ((size_t)b * T_ + tg + 8) * D_ + h * HD_;
#pragma unroll
    for (int nt = 0; nt < 16; nt++) {
        int e = nt * 8 + ((lane & 3) << 1);
        *(__half2*)(g_att + base0 + e) = __floats2half2_rn(o[nt][0] * inv0, o[nt][1] * inv0);
        *(__half2*)(g_att + base1 + e) = __floats2half2_rn(o[nt][2] * inv1, o[nt][3] * inv1);
    }
}

// ------------------------------------------------------------------
// Launch
// ------------------------------------------------------------------
extern "C" void kernel_launch(void* const* d_in, const int* in_sizes, int n_in,
                              void* d_out, int out_size) {
    const float* x   = (const float*)d_in[0];
    const float* Wq  = (const float*)d_in[1];
    const float* bq  = (const float*)d_in[2];
    const float* Wk  = (const float*)d_in[3];
    const float* bk  = (const float*)d_in[4];
    const float* Wv  = (const float*)d_in[5];
    const float* bv  = (const float*)d_in[6];
    const float* W1  = (const float*)d_in[7];
    const float* b1  = (const float*)d_in[8];
    const float* W2  = (const float*)d_in[9];
    const float* b2  = (const float*)d_in[10];
    const float* g1  = (const float*)d_in[11];
    const float* be1 = (const float*)d_in[12];
    const float* g2  = (const float*)d_in[13];
    const float* be2 = (const float*)d_in[14];
    float* out = (float*)d_out;

    __half *pWq, *pWk, *pWv, *pW1, *pW2, *pH, *pH2;
    cudaGetSymbolAddress((void**)&pWq, g_Wq);
    cudaGetSymbolAddress((void**)&pWk, g_Wk);
    cudaGetSymbolAddress((void**)&pWv, g_Wv);
    cudaGetSymbolAddress((void**)&pW1, g_W1);
    cudaGetSymbolAddress((void**)&pW2, g_W2);
    cudaGetSymbolAddress((void**)&pH,  g_h);
    cudaGetSymbolAddress((void**)&pH2, g_h2);

    const int nW  = H_ * D_ * HD_;   // 4,194,304
    const int nW1 = D_ * DFF_;       // 16,777,216

    f2h_kernel<<<(nW/8)  / 256, 256>>>((const float4*)Wq, (uint4*)pWq, nW/8);
    f2h_kernel<<<(nW/8)  / 256, 256>>>((const float4*)Wk, (uint4*)pWk, nW/8);
    f2h_kernel<<<(nW/8)  / 256, 256>>>((const float4*)Wv, (uint4*)pWv, nW/8);
    f2h_kernel<<<(nW1/8) / 256, 256>>>((const float4*)W1, (uint4*)pW1, nW1/8);
    f2h_kernel<<<(nW1/8) / 256, 256>>>((const float4*)W2, (uint4*)pW2, nW1/8);

    ln_kernel<<<R_, 256>>>(x, g1, be1, pH);

    cudaFuncSetAttribute(gemm_kernel, cudaFuncAttributeMaxDynamicSharedMemorySize, GSMEM);
    cudaFuncSetAttribute(attn_kernel, cudaFuncAttributeMaxDynamicSharedMemorySize, ASMEM);

    // QKV: N = 3*2048 = 6144
    gemm_kernel<<<dim3(6144 / BN, R_ / BM), 256, GSMEM>>>(0, bq, bk, bv, b1, b2, out);

    attn_kernel<<<dim3(T_ / AQ, B_ * H_), 128, ASMEM>>>();

    resid_ln_kernel<<<R_, 256>>>(x, g2, be2, out, pH2);

    gemm_kernel<<<dim3(DFF_ / BN, R_ / BM), 256, GSMEM>>>(1, bq, bk, bv, b1, b2, out);

    gemm_kernel<<<dim3(D_ / BN, R_ / BM), 256, GSMEM>>>(2, bq, bk, bv, b1, b2, out);
}

// round 7
// speedup vs baseline: 1.1346x; 1.0050x over previous
#include <cuda_runtime.h>
#include <cuda_fp16.h>
#include <cstdint>

// Problem constants
#define B_   4
#define T_   2048
#define D_   2048
#define H_   16
#define HD_  128
#define DFF_ 8192
#define R_   (B_*T_)      // 8192 rows

// ------------------------------------------------------------------
// Device scratch
// ------------------------------------------------------------------
__device__ __align__(256) __half g_h  [(size_t)R_*D_];
__device__ __align__(256) __half g_h2 [(size_t)R_*D_];
__device__ __align__(256) __half g_Wq [(size_t)H_*D_*HD_];
__device__ __align__(256) __half g_Wk [(size_t)H_*D_*HD_];
__device__ __align__(256) __half g_Wv [(size_t)H_*D_*HD_];
__device__ __align__(256) __half g_W1 [(size_t)D_*DFF_];
__device__ __align__(256) __half g_W2 [(size_t)DFF_*D_];
__device__ __align__(256) __half g_q  [(size_t)B_*H_*T_*HD_];
__device__ __align__(256) __half g_k  [(size_t)B_*H_*T_*HD_];
__device__ __align__(256) __half g_v  [(size_t)B_*H_*T_*HD_];
__device__ __align__(256) __half g_att[(size_t)R_*D_];
__device__ __align__(256) __half g_ff [(size_t)R_*DFF_];

// ------------------------------------------------------------------
// Helpers
// ------------------------------------------------------------------
__device__ __forceinline__ uint32_t smem_u32(const void* p) {
    return (uint32_t)__cvta_generic_to_shared(p);
}
__device__ __forceinline__ void cp16(uint32_t dst, const void* src) {
    asm volatile("cp.async.cg.shared.global [%0], [%1], 16;" :: "r"(dst), "l"(src));
}
#define CP_COMMIT() asm volatile("cp.async.commit_group;")
#define CP_WAIT0()  asm volatile("cp.async.wait_group 0;")
#define CP_WAIT1()  asm volatile("cp.async.wait_group 1;")

__device__ __forceinline__ void ldsm_x4(uint32_t& r0, uint32_t& r1, uint32_t& r2, uint32_t& r3, uint32_t a) {
    asm volatile("ldmatrix.sync.aligned.m8n8.x4.shared.b16 {%0,%1,%2,%3}, [%4];"
                 : "=r"(r0), "=r"(r1), "=r"(r2), "=r"(r3) : "r"(a));
}
__device__ __forceinline__ void ldsm_x4_t(uint32_t& r0, uint32_t& r1, uint32_t& r2, uint32_t& r3, uint32_t a) {
    asm volatile("ldmatrix.sync.aligned.m8n8.x4.trans.shared.b16 {%0,%1,%2,%3}, [%4];"
                 : "=r"(r0), "=r"(r1), "=r"(r2), "=r"(r3) : "r"(a));
}
__device__ __forceinline__ void mma_16816(float* c, const uint32_t* a, uint32_t b0, uint32_t b1v) {
    asm volatile(
        "mma.sync.aligned.m16n8k16.row.col.f32.f16.f16.f32 "
        "{%0,%1,%2,%3}, {%4,%5,%6,%7}, {%8,%9}, {%0,%1,%2,%3};\n"
        : "+f"(c[0]), "+f"(c[1]), "+f"(c[2]), "+f"(c[3])
        : "r"(a[0]), "r"(a[1]), "r"(a[2]), "r"(a[3]), "r"(b0), "r"(b1v));
}
__device__ __forceinline__ uint32_t packh2(float a, float b) {
    __half2 h = __floats2half2_rn(a, b);
    return *reinterpret_cast<uint32_t*>(&h);
}

// ------------------------------------------------------------------
// Fused LN1 + all weight fp32->fp16 conversions (ONE launch).
// Blocks [0, R_)          : LayerNorm of x -> g_h (fp16)
// Blocks [R_, R_+22528)   : vectorized f2h of Wq|Wk|Wv|W1|W2
// ------------------------------------------------------------------
#define NV8_QKV  524288            // 4,194,304 / 8
#define NV8_FF   2097152           // 16,777,216 / 8
#define F2H_BLOCKS ((3*NV8_QKV + 2*NV8_FF) / 256)   // 22528

__global__ void __launch_bounds__(256) ln_f2h_kernel(
    const float* __restrict__ x, const float* __restrict__ g,
    const float* __restrict__ b, __half* __restrict__ out,
    const float4* __restrict__ Wq, const float4* __restrict__ Wk,
    const float4* __restrict__ Wv, const float4* __restrict__ W1,
    const float4* __restrict__ W2,
    uint4* __restrict__ pWq, uint4* __restrict__ pWk, uint4* __restrict__ pWv,
    uint4* __restrict__ pW1, uint4* __restrict__ pW2)
{
    if (blockIdx.x >= R_) {
        // ---- f2h segment ----
        long i = (long)(blockIdx.x - R_) * 256 + threadIdx.x;   // vec8 index
        const float4* src; uint4* dst;
        if      (i < 1L*NV8_QKV)            { src = Wq; dst = pWq; }
        else if (i < 2L*NV8_QKV)            { src = Wk; dst = pWk; i -= 1L*NV8_QKV; }
        else if (i < 3L*NV8_QKV)            { src = Wv; dst = pWv; i -= 2L*NV8_QKV; }
        else if (i < 3L*NV8_QKV + NV8_FF)   { src = W1; dst = pW1; i -= 3L*NV8_QKV; }
        else                                { src = W2; dst = pW2; i -= 3L*NV8_QKV + NV8_FF; }
        float4 a = src[2*i], c = src[2*i + 1];
        __half2 h0 = __floats2half2_rn(a.x, a.y);
        __half2 h1 = __floats2half2_rn(a.z, a.w);
        __half2 h2 = __floats2half2_rn(c.x, c.y);
        __half2 h3 = __floats2half2_rn(c.z, c.w);
        uint4 o;
        o.x = *(uint32_t*)&h0; o.y = *(uint32_t*)&h1;
        o.z = *(uint32_t*)&h2; o.w = *(uint32_t*)&h3;
        dst[i] = o;
        return;
    }
    // ---- LayerNorm segment ----
    int r = blockIdx.x;
    size_t off = (size_t)r * D_;
    float v[8], s = 0.f, s2 = 0.f;
#pragma unroll
    for (int j = 0; j < 8; j++) {
        float val = x[off + threadIdx.x + j*256];
        v[j] = val; s += val; s2 += val*val;
    }
    __shared__ float red[32];
#pragma unroll
    for (int o = 16; o; o >>= 1) { s += __shfl_xor_sync(~0u, s, o); s2 += __shfl_xor_sync(~0u, s2, o); }
    int wid = threadIdx.x >> 5;
    if ((threadIdx.x & 31) == 0) { red[wid] = s; red[8 + wid] = s2; }
    __syncthreads();
    if (threadIdx.x < 32) {
        float a  = (threadIdx.x < 8) ? red[threadIdx.x]   : 0.f;
        float c2 = (threadIdx.x < 8) ? red[8+threadIdx.x] : 0.f;
#pragma unroll
        for (int o = 4; o; o >>= 1) { a += __shfl_xor_sync(~0u, a, o); c2 += __shfl_xor_sync(~0u, c2, o); }
        if (threadIdx.x == 0) { red[16] = a; red[17] = c2; }
    }
    __syncthreads();
    float mu  = red[16] * (1.f / D_);
    float var = red[17] * (1.f / D_) - mu * mu;
    float rs  = rsqrtf(var + 1e-5f);
#pragma unroll
    for (int j = 0; j < 8; j++) {
        int c = threadIdx.x + j*256;
        out[off + c] = __float2half((v[j] - mu) * rs * g[c] + b[c]);
    }
}

// Fused: x1 = x + att ; write x1 to xout (fp32) ; h2 = LN(x1)
__global__ void __launch_bounds__(256) resid_ln_kernel(
    const float* __restrict__ x, const float* __restrict__ g,
    const float* __restrict__ b, float* __restrict__ xout,
    __half* __restrict__ h2)
{
    int r = blockIdx.x;
    size_t off = (size_t)r * D_;
    float v[8], s = 0.f, s2 = 0.f;
#pragma unroll
    for (int j = 0; j < 8; j++) {
        int c = threadIdx.x + j*256;
        float val = x[off + c] + __half2float(g_att[off + c]);
        xout[off + c] = val;
        v[j] = val; s += val; s2 += val*val;
    }
    __shared__ float red[32];
#pragma unroll
    for (int o = 16; o; o >>= 1) { s += __shfl_xor_sync(~0u, s, o); s2 += __shfl_xor_sync(~0u, s2, o); }
    int wid = threadIdx.x >> 5;
    if ((threadIdx.x & 31) == 0) { red[wid] = s; red[8 + wid] = s2; }
    __syncthreads();
    if (threadIdx.x < 32) {
        float a  = (threadIdx.x < 8) ? red[threadIdx.x]   : 0.f;
        float c2 = (threadIdx.x < 8) ? red[8+threadIdx.x] : 0.f;
#pragma unroll
        for (int o = 4; o; o >>= 1) { a += __shfl_xor_sync(~0u, a, o); c2 += __shfl_xor_sync(~0u, c2, o); }
        if (threadIdx.x == 0) { red[16] = a; red[17] = c2; }
    }
    __syncthreads();
    float mu  = red[16] * (1.f / D_);
    float var = red[17] * (1.f / D_) - mu * mu;
    float rs  = rsqrtf(var + 1e-5f);
#pragma unroll
    for (int j = 0; j < 8; j++) {
        int c = threadIdx.x + j*256;
        h2[off + c] = __float2half((v[j] - mu) * rs * g[c] + b[c]);
    }
}

// ------------------------------------------------------------------
// GEMM: C[M,N] = A[M,K]*B[K,N], 3-stage cp.async, ldmatrix, swizzled.
// BM=128, BN=128, BK=64; 256 threads (2x4 warps), warp tile 64x32.
// 2 CTAs/SM, one __syncthreads per k-tile.
//   mode 0: QKV   mode 1: FFN1 (relu)   mode 2: FFN2 (xout += C + b2)
// ------------------------------------------------------------------
#define BM 128
#define BN 128
#define BK 64
#define ASTG (BM*BK*2)            // 16384 B
#define BSTG (BK*BN*2)            // 16384 B
#define STG  (ASTG + BSTG)        // 32768 B
#define GSMEM (3*STG)             // 98304 B

__global__ void __launch_bounds__(256, 2) gemm_kernel(
    int mode,
    const float* __restrict__ bq, const float* __restrict__ bk, const float* __restrict__ bv,
    const float* __restrict__ b1, const float* __restrict__ b2,
    float* __restrict__ xout)
{
    const __half* A; int K;
    if (mode == 0)      { A = g_h;  K = D_;   }
    else if (mode == 1) { A = g_h2; K = D_;   }
    else                { A = g_ff; K = DFF_; }

    const int m0 = blockIdx.y * BM;
    const int n0 = blockIdx.x * BN;
    const int nkt = K / BK;

    extern __shared__ __half dsm[];
    const uint32_t sbase = smem_u32(dsm);

    const int tid  = threadIdx.x;
    const int wid  = tid >> 5;
    const int lane = tid & 31;
    const int wm   = wid & 1;               // 0..1 (M half, 64 rows)
    const int wn   = wid >> 1;              // 0..3 (N quarter, 32 cols)

    float acc[4][4][4];
#pragma unroll
    for (int i = 0; i < 4; i++)
#pragma unroll
        for (int j = 0; j < 4; j++)
#pragma unroll
            for (int q = 0; q < 4; q++) acc[i][j][q] = 0.f;

    // ---- stage loader ----
    auto loadStage = [&](int kt, int s) {
        uint32_t sA = sbase + s * STG;
        uint32_t sB = sA + ASTG;
#pragma unroll
        for (int i = 0; i < 4; i++) {
            int idx = tid + i * 256;
            int r = idx >> 3, c = idx & 7;
            int sc = c ^ (r & 7);
            cp16(sA + r * 128 + sc * 16, A + (size_t)(m0 + r) * K + kt * BK + c * 8);
        }
#pragma unroll
        for (int i = 0; i < 4; i++) {
            int idx = tid + i * 256;
            int r = idx >> 4, c = idx & 15;
            int sc = ((c & 7) ^ (r & 7)) | (c & 8);
            int n = n0 + c * 8;
            const __half* src;
            if (mode == 0) {
                int which = n >> 11, head = (n >> 7) & 15, e = n & 127;
                const __half* W = (which == 0) ? g_Wq : (which == 1) ? g_Wk : g_Wv;
                src = W + (size_t)head * (D_ * HD_) + (size_t)(kt * BK + r) * HD_ + e;
            } else if (mode == 1) {
                src = g_W1 + (size_t)(kt * BK + r) * DFF_ + n;
            } else {
                src = g_W2 + (size_t)(kt * BK + r) * D_ + n;
            }
            cp16(sB + r * 256 + sc * 16, src);
        }
    };

    loadStage(0, 0); CP_COMMIT();
    loadStage(1, 1); CP_COMMIT();

    for (int kt = 0; kt < nkt; kt++) {
        if (kt + 1 < nkt) { CP_WAIT1(); } else { CP_WAIT0(); }
        __syncthreads();
        if (kt + 2 < nkt) { loadStage(kt + 2, (kt + 2) % 3); CP_COMMIT(); }

        uint32_t sA = sbase + (kt % 3) * STG;
        uint32_t sB = sA + ASTG;

#pragma unroll
        for (int kk = 0; kk < 4; kk++) {
            uint32_t a[4][4];
#pragma unroll
            for (int mt = 0; mt < 4; mt++) {
                int row = wm * 64 + mt * 16 + (lane & 15);
                int ch  = 2 * kk + (lane >> 4);
                ldsm_x4(a[mt][0], a[mt][1], a[mt][2], a[mt][3],
                        sA + row * 128 + ((ch ^ (row & 7)) << 4));
            }
            uint32_t bf[4][2];
#pragma unroll
            for (int ntp = 0; ntp < 2; ntp++) {
                int row = kk * 16 + ((lane >> 3) & 1) * 8 + (lane & 7);
                int ch  = wn * 4 + ntp * 2 + (lane >> 4);
                int sc  = ((ch & 7) ^ (row & 7)) | (ch & 8);
                ldsm_x4_t(bf[2*ntp][0], bf[2*ntp][1], bf[2*ntp+1][0], bf[2*ntp+1][1],
                          sB + row * 256 + sc * 16);
            }
#pragma unroll
            for (int nt = 0; nt < 4; nt++)
#pragma unroll
                for (int mt = 0; mt < 4; mt++)
                    mma_16816(acc[mt][nt], a[mt], bf[nt][0], bf[nt][1]);
        }
    }

    // ---- Epilogue ----
    if (mode == 0) {
        int which = n0 >> 11, head = (n0 >> 7) & 15;
        const float* bias = ((which == 0) ? bq : (which == 1) ? bk : bv) + head * HD_;
        __half* qkv = (which == 0) ? g_q : (which == 1) ? g_k : g_v;
#pragma unroll
        for (int mt = 0; mt < 4; mt++) {
#pragma unroll
            for (int nt = 0; nt < 4; nt++) {
                float* cc = acc[mt][nt];
                int row0 = m0 + wm * 64 + mt * 16 + (lane >> 2);
                int e    = wn * 32 + nt * 8 + ((lane & 3) << 1);
                float bb0 = bias[e], bb1 = bias[e + 1];
#pragma unroll
                for (int rr = 0; rr < 2; rr++) {
                    int row = row0 + rr * 8;
                    int bb = row >> 11, t = row & (T_ - 1);
                    __half* dst = qkv + (((size_t)(bb * H_ + head) * T_ + t) * HD_) + e;
                    *(__half2*)dst = __floats2half2_rn(cc[rr*2] + bb0, cc[rr*2+1] + bb1);
                }
            }
        }
    } else if (mode == 1) {
#pragma unroll
        for (int mt = 0; mt < 4; mt++) {
#pragma unroll
            for (int nt = 0; nt < 4; nt++) {
                float* cc = acc[mt][nt];
                int row0 = m0 + wm * 64 + mt * 16 + (lane >> 2);
                int col  = n0 + wn * 32 + nt * 8 + ((lane & 3) << 1);
                float bb0 = b1[col], bb1 = b1[col + 1];
#pragma unroll
                for (int rr = 0; rr < 2; rr++) {
                    int row = row0 + rr * 8;
                    float v0 = fmaxf(cc[rr*2]   + bb0, 0.f);
                    float v1 = fmaxf(cc[rr*2+1] + bb1, 0.f);
                    *(__half2*)(g_ff + (size_t)row * DFF_ + col) = __floats2half2_rn(v0, v1);
                }
            }
        }
    } else {
#pragma unroll
        for (int mt = 0; mt < 4; mt++) {
#pragma unroll
            for (int nt = 0; nt < 4; nt++) {
                float* cc = acc[mt][nt];
                int row0 = m0 + wm * 64 + mt * 16 + (lane >> 2);
                int col  = n0 + wn * 32 + nt * 8 + ((lane & 3) << 1);
                float bb0 = b2[col], bb1 = b2[col + 1];
#pragma unroll
                for (int rr = 0; rr < 2; rr++) {
                    int row = row0 + rr * 8;
                    float2* d = (float2*)(xout + (size_t)row * D_ + col);
                    float2 val = *d;
                    val.x += cc[rr*2]   + bb0;
                    val.y += cc[rr*2+1] + bb1;
                    *d = val;
                }
            }
        }
    }
}

// ------------------------------------------------------------------
// Flash attention: grid (T/64, B*H), 128 threads (4 warps x 16 q rows)
// Double-buffered cp.async K/V (2 x 32KB dynamic smem).
// ------------------------------------------------------------------
#define AQ 64
#define AK 64
#define AKVSTG (AK*HD_*2)          // 16384 B per tensor per stage
#define ASMEM  (4*AKVSTG)          // 65536 B

__global__ void __launch_bounds__(128) attn_kernel() {
    const int bh = blockIdx.y;
    const int b  = bh >> 4, h = bh & 15;
    const int t0 = blockIdx.x * AQ;

    const __half* qbase = g_q + (size_t)bh * T_ * HD_;
    const __half* kbase = g_k + (size_t)bh * T_ * HD_;
    const __half* vbase = g_v + (size_t)bh * T_ * HD_;

    extern __shared__ __half kvsm[];
    const uint32_t kvbase = smem_u32(kvsm);

    const int tid  = threadIdx.x;
    const int wid  = tid >> 5;
    const int lane = tid & 31;
    const int qr   = wid * 16 + (lane >> 2);

    // Q fragments in registers
    uint32_t qa[8][4];
    {
        const __half* qp = qbase + (size_t)t0 * HD_;
#pragma unroll
        for (int kk = 0; kk < 8; kk++) {
            int c = ((lane & 3) << 1) + kk * 16;
            qa[kk][0] = *(const uint32_t*)(qp + (size_t)qr       * HD_ + c);
            qa[kk][1] = *(const uint32_t*)(qp + (size_t)(qr + 8) * HD_ + c);
            qa[kk][2] = *(const uint32_t*)(qp + (size_t)qr       * HD_ + c + 8);
            qa[kk][3] = *(const uint32_t*)(qp + (size_t)(qr + 8) * HD_ + c + 8);
        }
    }

    float m_run[2] = {-1e30f, -1e30f};
    float l_run[2] = {0.f, 0.f};
    float o[16][4];
#pragma unroll
    for (int i = 0; i < 16; i++)
#pragma unroll
        for (int q = 0; q < 4; q++) o[i][q] = 0.f;

    const float scale = 0.08838834764831845f;
    const int jmax = t0 / AK;

    auto loadKV = [&](int j, int s) {
        uint32_t kb = kvbase + s * (2 * AKVSTG);
        uint32_t vb = kb + AKVSTG;
        const __half* ks = kbase + (size_t)(j * AK) * HD_;
        const __half* vs = vbase + (size_t)(j * AK) * HD_;
#pragma unroll
        for (int i = 0; i < 8; i++) {
            int idx = tid + i * 128;
            int row = idx >> 4, ch = idx & 15;
            int sc = ((ch & 7) ^ (row & 7)) | (ch & 8);
            cp16(kb + row * 256 + sc * 16, ks + (size_t)row * HD_ + ch * 8);
            cp16(vb + row * 256 + sc * 16, vs + (size_t)row * HD_ + ch * 8);
        }
    };

    loadKV(0, 0); CP_COMMIT();

    for (int j = 0; j <= jmax; j++) {
        const int s0 = j * AK;
        __syncthreads();
        if (j + 1 <= jmax) { loadKV(j + 1, (j + 1) & 1); CP_COMMIT(); CP_WAIT1(); }
        else               { CP_WAIT0(); }
        __syncthreads();

        uint32_t Kb = kvbase + (j & 1) * (2 * AKVSTG);
        uint32_t Vb = Kb + AKVSTG;

        // S = Q K^T
        float sacc[8][4];
#pragma unroll
        for (int nt = 0; nt < 8; nt++)
#pragma unroll
            for (int q = 0; q < 4; q++) sacc[nt][q] = 0.f;

#pragma unroll
        for (int kk = 0; kk < 8; kk++) {
#pragma unroll
            for (int ntp = 0; ntp < 4; ntp++) {
                int row = ntp * 16 + ((lane >> 4) << 3) + (lane & 7);
                int ch  = 2 * kk + ((lane >> 3) & 1);
                int sc  = ((ch & 7) ^ (row & 7)) | (ch & 8);
                uint32_t r0, r1, r2, r3;
                ldsm_x4(r0, r1, r2, r3, Kb + row * 256 + sc * 16);
                mma_16816(sacc[2*ntp],   qa[kk], r0, r1);
                mma_16816(sacc[2*ntp+1], qa[kk], r2, r3);
            }
        }

        // scale + causal mask + tile max
        const int tg0 = t0 + wid * 16 + (lane >> 2);
        float mtile[2] = {-1e30f, -1e30f};
#pragma unroll
        for (int nt = 0; nt < 8; nt++) {
            int sg = s0 + nt * 8 + ((lane & 3) << 1);
#pragma unroll
            for (int q = 0; q < 4; q++) {
                int rsel = q >> 1;
                int scol = sg + (q & 1);
                int tg   = tg0 + (rsel ? 8 : 0);
                float vv = sacc[nt][q] * scale;
                if (scol > tg) vv = -1e30f;
                sacc[nt][q] = vv;
                mtile[rsel] = fmaxf(mtile[rsel], vv);
            }
        }
#pragma unroll
        for (int o2 = 1; o2 < 4; o2 <<= 1) {
            mtile[0] = fmaxf(mtile[0], __shfl_xor_sync(~0u, mtile[0], o2));
            mtile[1] = fmaxf(mtile[1], __shfl_xor_sync(~0u, mtile[1], o2));
        }
        float mnew[2] = {fmaxf(m_run[0], mtile[0]), fmaxf(m_run[1], mtile[1])};
        float corr[2] = {__expf(m_run[0] - mnew[0]), __expf(m_run[1] - mnew[1])};

        // P = exp(S - m)
        float pl[2] = {0.f, 0.f};
        uint32_t pa[4][4];
#pragma unroll
        for (int nt = 0; nt < 8; nt++) {
            float p0 = __expf(sacc[nt][0] - mnew[0]);
            float p1 = __expf(sacc[nt][1] - mnew[0]);
            float p2 = __expf(sacc[nt][2] - mnew[1]);
            float p3 = __expf(sacc[nt][3] - mnew[1]);
            pl[0] += p0 + p1; pl[1] += p2 + p3;
            int kk2 = nt >> 1, hi = nt & 1;
            pa[kk2][2*hi]     = packh2(p0, p1);
            pa[kk2][2*hi + 1] = packh2(p2, p3);
        }
#pragma unroll
        for (int o2 = 1; o2 < 4; o2 <<= 1) {
            pl[0] += __shfl_xor_sync(~0u, pl[0], o2);
            pl[1] += __shfl_xor_sync(~0u, pl[1], o2);
        }
        l_run[0] = l_run[0] * corr[0] + pl[0];
        l_run[1] = l_run[1] * corr[1] + pl[1];
        m_run[0] = mnew[0]; m_run[1] = mnew[1];

        // rescale O, then O += P @ V
#pragma unroll
        for (int nt = 0; nt < 16; nt++) {
            o[nt][0] *= corr[0]; o[nt][1] *= corr[0];
            o[nt][2] *= corr[1]; o[nt][3] *= corr[1];
        }
#pragma unroll
        for (int kk2 = 0; kk2 < 4; kk2++) {
#pragma unroll
            for (int etp = 0; etp < 8; etp++) {
                int row = kk2 * 16 + ((lane >> 3) & 1) * 8 + (lane & 7);
                int ch  = etp * 2 + (lane >> 4);
                int sc  = ((ch & 7) ^ (row & 7)) | (ch & 8);
                uint32_t r0, r1, r2, r3;
                ldsm_x4_t(r0, r1, r2, r3, Vb + row * 256 + sc * 16);
                mma_16816(o[2*etp],   pa[kk2], r0, r1);
                mma_16816(o[2*etp+1], pa[kk2], r2, r3);
            }
        }
    }

    // write normalized O
    float inv0 = 1.f / l_run[0], inv1 = 1.f / l_run[1];
    const int tg = t0 + wid * 16 + (lane >> 2);
    size_t base0 = ((size_t)b * T_ + tg)     * D_ + h * HD_;
    size_t base1 = ((size_t)b * T_ + tg + 8) * D_ + h * HD_;
#pragma unroll
    for (int nt = 0; nt < 16; nt++) {
        int e = nt * 8 + ((lane & 3) << 1);
        *(__half2*)(g_att + base0 + e) = __floats2half2_rn(o[nt][0] * inv0, o[nt][1] * inv0);
        *(__half2*)(g_att + base1 + e) = __floats2half2_rn(o[nt][2] * inv1, o[nt][3] * inv1);
    }
}

// ------------------------------------------------------------------
// Launch
// ------------------------------------------------------------------
extern "C" void kernel_launch(void* const* d_in, const int* in_sizes, int n_in,
                              void* d_out, int out_size) {
    const float* x   = (const float*)d_in[0];
    const float* Wq  = (const float*)d_in[1];
    const float* bq  = (const float*)d_in[2];
    const float* Wk  = (const float*)d_in[3];
    const float* bk  = (const float*)d_in[4];
    const float* Wv  = (const float*)d_in[5];
    const float* bv  = (const float*)d_in[6];
    const float* W1  = (const float*)d_in[7];
    const float* b1  = (const float*)d_in[8];
    const float* W2  = (const float*)d_in[9];
    const float* b2  = (const float*)d_in[10];
    const float* g1  = (const float*)d_in[11];
    const float* be1 = (const float*)d_in[12];
    const float* g2  = (const float*)d_in[13];
    const float* be2 = (const float*)d_in[14];
    float* out = (float*)d_out;

    __half *pWq, *pWk, *pWv, *pW1, *pW2, *pH, *pH2;
    cudaGetSymbolAddress((void**)&pWq, g_Wq);
    cudaGetSymbolAddress((void**)&pWk, g_Wk);
    cudaGetSymbolAddress((void**)&pWv, g_Wv);
    cudaGetSymbolAddress((void**)&pW1, g_W1);
    cudaGetSymbolAddress((void**)&pW2, g_W2);
    cudaGetSymbolAddress((void**)&pH,  g_h);
    cudaGetSymbolAddress((void**)&pH2, g_h2);

    cudaFuncSetAttribute(gemm_kernel, cudaFuncAttributeMaxDynamicSharedMemorySize, GSMEM);
    cudaFuncSetAttribute(attn_kernel, cudaFuncAttributeMaxDynamicSharedMemorySize, ASMEM);

    // Launch 1: fused LN1 + all weight conversions
    ln_f2h_kernel<<<R_ + F2H_BLOCKS, 256>>>(
        x, g1, be1, pH,
        (const float4*)Wq, (const float4*)Wk, (const float4*)Wv,
        (const float4*)W1, (const float4*)W2,
        (uint4*)pWq, (uint4*)pWk, (uint4*)pWv, (uint4*)pW1, (uint4*)pW2);

    // Launch 2: QKV GEMM (N = 3*2048 = 6144)
    gemm_kernel<<<dim3(6144 / BN, R_ / BM), 256, GSMEM>>>(0, bq, bk, bv, b1, b2, out);

    // Launch 3: attention
    attn_kernel<<<dim3(T_ / AQ, B_ * H_), 128, ASMEM>>>();

    // Launch 4: residual + LN2
    resid_ln_kernel<<<R_, 256>>>(x, g2, be2, out, pH2);

    // Launch 5: FFN1  (ncu -s 5 -c 1 should land here)
    gemm_kernel<<<dim3(DFF_ / BN, R_ / BM), 256, GSMEM>>>(1, bq, bk, bv, b1, b2, out);

    // Launch 6: FFN2
    gemm_kernel<<<dim3(D_ / BN, R_ / BM), 256, GSMEM>>>(2, bq, bk, bv, b1, b2, out);
}